// round 11
// baseline (speedup 1.0000x reference)
#include <cuda_runtime.h>
#include <cuda_bf16.h>
#include <cstdint>

// ---------------------------------------------------------------------------
// TotalAttention — FULLY FUSED: one kernel per window (qkv GEMM + attention +
// out-proj). qkv intermediate lives only in smem (no DRAM round trip).
//   0) pack_w: wq(*scale)|wkv -> transposed split planes [768][256]; wp planes;
//      biases; bias table g_bias[h][n][m]
//   1) fused_all (4096 blocks x 512 thr):
//      - x[64][256] fp32 -> registers (8 float4/thread)
//      - per head-pair hp (N=192 strip of wqkv): 3xBF16 GEMM (A split
//        in-kernel, B planes streamed L2->smem) -> q/k/v fp32 in smem
//      - attention for 2 heads (3xTF32, 4 warps/head x 16 rows) -> O bf16
//        hi/res planes in smem (AO)
//      - after 4 hp: out = AO @ wp^T + bp (3xBF16, wp streamed) -> d_out
// mma.sync only (tcgen05 unsupported on this bench's compute_103 ptxas path).
// ---------------------------------------------------------------------------

#define B_WIN   4096
#define N_TOK   64
#define DIM_C   256
#define HEADS   8
#define HDIM    32
#define M_ROWS  (B_WIN * N_TOK)
#define QKV_LD  768
#define SCALE_F 0.17677669529663687f

__device__ unsigned short g_wthi [QKV_LD * DIM_C];          // wqkv^T [768][256]
__device__ unsigned short g_wtres[QKV_LD * DIM_C];
__device__ unsigned short g_wpthi [DIM_C * DIM_C];          // wp^T [256][256]
__device__ unsigned short g_wptres[DIM_C * DIM_C];
__device__ float g_bqkv[QKV_LD];
__device__ float g_bias[HEADS * N_TOK * N_TOK];             // [h][n][m]

// ---------------------------------------------------------------------------
__device__ __forceinline__ void cp_async16(void* smem_dst, const void* gsrc) {
    unsigned saddr = (unsigned)__cvta_generic_to_shared(smem_dst);
    asm volatile("cp.async.cg.shared.global [%0], [%1], 16;\n"
                 :: "r"(saddr), "l"(gsrc));
}

__device__ __forceinline__ void ldsm_x4(unsigned* r, const void* p) {
    unsigned a = (unsigned)__cvta_generic_to_shared(p);
    asm volatile("ldmatrix.sync.aligned.m8n8.x4.shared.b16 {%0,%1,%2,%3}, [%4];"
                 : "=r"(r[0]), "=r"(r[1]), "=r"(r[2]), "=r"(r[3]) : "r"(a));
}

__device__ __forceinline__ void ldsm_x2(unsigned* r, const void* p) {
    unsigned a = (unsigned)__cvta_generic_to_shared(p);
    asm volatile("ldmatrix.sync.aligned.m8n8.x2.shared.b16 {%0,%1}, [%2];"
                 : "=r"(r[0]), "=r"(r[1]) : "r"(a));
}

__device__ __forceinline__ void mma_bf16(float* c, const unsigned* a, const unsigned* b) {
    asm volatile(
        "mma.sync.aligned.m16n8k16.row.col.f32.bf16.bf16.f32 "
        "{%0,%1,%2,%3}, {%4,%5,%6,%7}, {%8,%9}, {%0,%1,%2,%3};\n"
        : "+f"(c[0]), "+f"(c[1]), "+f"(c[2]), "+f"(c[3])
        : "r"(a[0]), "r"(a[1]), "r"(a[2]), "r"(a[3]),
          "r"(b[0]), "r"(b[1]));
}

__device__ __forceinline__ void mma_tf32(float* c, const unsigned* a, const unsigned* b) {
    asm volatile(
        "mma.sync.aligned.m16n8k8.row.col.f32.tf32.tf32.f32 "
        "{%0,%1,%2,%3}, {%4,%5,%6,%7}, {%8,%9}, {%0,%1,%2,%3};\n"
        : "+f"(c[0]), "+f"(c[1]), "+f"(c[2]), "+f"(c[3])
        : "r"(a[0]), "r"(a[1]), "r"(a[2]), "r"(a[3]),
          "r"(b[0]), "r"(b[1]));
}

__device__ __forceinline__ void tf32_split(float f, unsigned& hi, unsigned& res) {
    hi  = __float_as_uint(f) & 0xFFFFE000u;
    res = __float_as_uint(f - __uint_as_float(hi));
}

__device__ __forceinline__ void bf16_split(float f, unsigned short& hi, unsigned short& res) {
    __nv_bfloat16 h = __float2bfloat16_rn(f);
    float r = f - __bfloat162float(h);
    hi  = __bfloat16_as_ushort(h);
    res = __bfloat16_as_ushort(__float2bfloat16_rn(r));
}

__device__ __forceinline__ void bf16_split_pack(float a, float b, unsigned& hi, unsigned& res) {
    unsigned short ha, ra, hb, rb;
    bf16_split(a, ha, ra);
    bf16_split(b, hb, rb);
    hi  = (unsigned)ha | ((unsigned)hb << 16);
    res = (unsigned)ra | ((unsigned)rb << 16);
}

// ---------------------------------------------------------------------------
__global__ void pack_w(const float* __restrict__ wq, const float* __restrict__ bq,
                       const float* __restrict__ wkv, const float* __restrict__ bkv,
                       const float* __restrict__ wp,
                       const float* __restrict__ rpb, const int* __restrict__ relidx)
{
    int i = blockIdx.x * blockDim.x + threadIdx.x;
    if (i < QKV_LD * DIM_C) {                 // wqkv^T: [n=768][k=256]
        int n = i / DIM_C, k = i % DIM_C;
        float v = (n < DIM_C) ? wq[k * DIM_C + n] * SCALE_F
                              : wkv[k * 512 + (n - DIM_C)];
        bf16_split(v, g_wthi[i], g_wtres[i]);
    }
    if (i < DIM_C * DIM_C) {                  // wp^T: [n=256][k=256]
        int n = i / DIM_C, k = i % DIM_C;
        bf16_split(wp[k * DIM_C + n], g_wpthi[i], g_wptres[i]);
    }
    if (i < QKV_LD) g_bqkv[i] = (i < DIM_C) ? bq[i] * SCALE_F : bkv[i - DIM_C];
    if (i < HEADS * N_TOK * N_TOK) {
        int h = i >> 12, nm = i & 4095;
        g_bias[i] = rpb[relidx[nm] * HEADS + h];
    }
}

// ---------------------------------------------------------------------------
// Fused kernel smem map (shorts unless noted):
//  [0,      10240)  A slice bufs: 2 x (hi 2560 | res 2560)
//  [10240,  40960)  B slice bufs: 2 x (hi 7680 | res 7680)
//  [40960,  68608)  QKV region: 2 heads x 6912 FLOATS (float idx 20480..34304)
//  [68608, 102400)  AO planes: hi 16896 | res 16896
//  phase 3: wp bufs 2 x (hi 10240 | res 10240) alias [0, 40960)
// ---------------------------------------------------------------------------
#define TPAD 40
#define A_SLICE (64 * TPAD)            // 2560 shorts/plane
#define A_BUF   (2 * A_SLICE)          // 5120 shorts (hi+res)
#define B_BASE  (2 * A_BUF)            // 10240
#define B_SLICE (192 * TPAD)           // 7680 shorts/plane
#define B_BUF   (2 * B_SLICE)          // 15360 shorts
#define QKV_FBASE 20480                // float index
#define HEAD_F  6912                   // floats per head (Q 64x36|K 64x36|V 64x36)
#define PS_STRIDE 68
#define AO_BASE_S 68608
#define AO_STRIDE 264
#define AO_PLANE  (64 * AO_STRIDE)     // 16896 shorts
#define WP_PLANE  (256 * TPAD)         // 10240 shorts
#define WP_BUF    (2 * WP_PLANE)       // 20480 shorts
#define FUSED_SMEM 204800              // bytes

__global__ __launch_bounds__(512)
void fused_all(const float* __restrict__ x,
               const float* __restrict__ bias_tab,
               const unsigned short* __restrict__ Whi,
               const unsigned short* __restrict__ Wres,
               const float* __restrict__ bqkv,
               const unsigned short* __restrict__ WPhi,
               const unsigned short* __restrict__ WPres,
               const float* __restrict__ bp,
               float* __restrict__ out)
{
    extern __shared__ __align__(16) unsigned short smu[];
    float* smf = (float*)smu;

    const int b    = blockIdx.x;
    const int tid  = threadIdx.x;
    const int warp = tid >> 5, lane = tid & 31;
    const int g = lane >> 2, t = lane & 3;

    // GEMM warp mapping: 2m x 8n grid, tile 32m x 24n
    const int wm2 = warp >> 3, wn = warp & 7;
    const int la_row = lane & 15, la_col = (lane >> 4) * 8;
    const int lb_row = lane & 7,  lb_col = ((lane >> 3) & 1) * 8;

    // ---- x -> registers (whole 64x256 tile of this window) ----
    const int xrow = tid >> 3, xcb = (tid & 7) * 4;
    float4 xr[8];
#pragma unroll
    for (int j = 0; j < 8; j++)
        xr[j] = *(const float4*)(x + ((size_t)b * 64 + xrow) * 256 + j * 32 + xcb);

    // ---- B slice fill: head-pair hp, k-slice kt ----
    auto issue_B = [&](int hp, int kt, int buf) {
        unsigned short* bh = smu + B_BASE + buf * B_BUF;
        unsigned short* br = bh + B_SLICE;
#pragma unroll
        for (int i = 0; i < 3; i++) {
            int j = tid + 512 * i;                 // 0..1535 chunks
            int plane = (j >= 768);
            int jj = plane ? j - 768 : j;
            int r = jj >> 2, ch = (jj & 3) * 8;
            int n = (r >> 6) * 256 + hp * 64 + (r & 63);
            const unsigned short* src = (plane ? Wres : Whi) + n * 256 + kt * 32 + ch;
            cp_async16((plane ? br : bh) + r * TPAD + ch, src);
        }
        asm volatile("cp.async.commit_group;\n");
    };

    issue_B(0, 0, 0);

    for (int hp = 0; hp < 4; ++hp) {
        float acc[2][3][4];
#pragma unroll
        for (int mt = 0; mt < 2; mt++)
#pragma unroll
            for (int nt = 0; nt < 3; nt++)
#pragma unroll
                for (int r = 0; r < 4; r++) acc[mt][nt][r] = 0.0f;

        for (int kt = 0; kt < 8; ++kt) {
            asm volatile("cp.async.wait_group 0;\n" ::: "memory");

            // split x slice kt -> A planes (buffer kt&1)
            {
                unsigned short* ah = smu + (kt & 1) * A_BUF;
                unsigned short* ar = ah + A_SLICE;
                unsigned h0, r0w, h1, r1w;
                bf16_split_pack(xr[kt].x, xr[kt].y, h0, r0w);
                bf16_split_pack(xr[kt].z, xr[kt].w, h1, r1w);
                const int off = xrow * TPAD + xcb;
                *(unsigned long long*)&ah[off] =
                    (unsigned long long)h0 | ((unsigned long long)h1 << 32);
                *(unsigned long long*)&ar[off] =
                    (unsigned long long)r0w | ((unsigned long long)r1w << 32);
            }
            __syncthreads();

            if (kt + 1 < 8)            issue_B(hp, kt + 1, (kt + 1) & 1);
            else if (hp + 1 < 4)       issue_B(hp + 1, 0, 0);   // runs during attn

            const unsigned short* As_hi  = smu + (kt & 1) * A_BUF;
            const unsigned short* As_res = As_hi + A_SLICE;
            const unsigned short* Bs_hi  = smu + B_BASE + (kt & 1) * B_BUF;
            const unsigned short* Bs_res = Bs_hi + B_SLICE;

#pragma unroll
            for (int ks = 0; ks < 2; ++ks) {
                const int ck = ks * 16;
                unsigned bh[3][2], br[3][2];
#pragma unroll
                for (int nt = 0; nt < 3; nt++) {
                    const int boff = (wn * 24 + nt * 8 + lb_row) * TPAD + ck + lb_col;
                    ldsm_x2(bh[nt], Bs_hi  + boff);
                    ldsm_x2(br[nt], Bs_res + boff);
                }
#pragma unroll
                for (int mt = 0; mt < 2; mt++) {
                    const int aoff = (wm2 * 32 + mt * 16 + la_row) * TPAD + ck + la_col;
                    unsigned ah[4], ar[4];
                    ldsm_x4(ah, As_hi  + aoff);
                    ldsm_x4(ar, As_res + aoff);
#pragma unroll
                    for (int nt = 0; nt < 3; nt++) {
                        mma_bf16(acc[mt][nt], ar, bh[nt]);
                        mma_bf16(acc[mt][nt], ah, br[nt]);
                        mma_bf16(acc[mt][nt], ah, bh[nt]);
                    }
                }
            }
            __syncthreads();
        }

        // ---- GEMM epilogue: acc + bias -> q/k/v smem (attention layout) ----
#pragma unroll
        for (int mt = 0; mt < 2; mt++) {
            const int r0 = wm2 * 32 + mt * 16 + g;
#pragma unroll
            for (int nt = 0; nt < 3; nt++) {
                const int col = wn * 24 + nt * 8 + 2 * t;
                const int region = col >> 6;       // 0=q 1=k 2=v (uniform per nt)
                const int c2 = col & 63;
                const int hs = c2 >> 5, cc = c2 & 31;
                const float b0 = bqkv[region * 256 + hp * 64 + c2];
                const float b1 = bqkv[region * 256 + hp * 64 + c2 + 1];
                float* reg = smf + QKV_FBASE + hs * HEAD_F + region * 2304;
                *(float2*)&reg[r0 * 36 + cc] =
                    make_float2(acc[mt][nt][0] + b0, acc[mt][nt][1] + b1);
                *(float2*)&reg[(r0 + 8) * 36 + cc] =
                    make_float2(acc[mt][nt][2] + b0, acc[mt][nt][3] + b1);
            }
        }
        __syncthreads();

        // ---- attention for heads 2hp, 2hp+1 (warps 0..7; 4 warps/head) ----
        const int hs = warp >> 2;                 // head slot 0/1 (warps < 8)
        const int wr = warp & 3;                  // 16-row group
        const int hg = 2 * hp + hs;
        float* QS = smf + QKV_FBASE + hs * HEAD_F;
        float* KS = QS + 2304;
        float* VS = QS + 4608;
        float* PS = QS;                           // aliases Q+K (4352 <= 4608)

        float s_[8][4];
        if (warp < 8) {
#pragma unroll
            for (int nt = 0; nt < 8; nt++)
#pragma unroll
                for (int r = 0; r < 4; r++) s_[nt][r] = 0.0f;

#pragma unroll
            for (int ks = 0; ks < 4; ++ks) {
                const int ck = ks * 8;
                unsigned ah[4], ar[4];
                const float* p = QS + (wr * 16 + g) * 36 + ck + t;
                tf32_split(p[0],          ah[0], ar[0]);
                tf32_split(p[8 * 36],     ah[1], ar[1]);
                tf32_split(p[4],          ah[2], ar[2]);
                tf32_split(p[8 * 36 + 4], ah[3], ar[3]);
#pragma unroll
                for (int nt = 0; nt < 8; nt++) {
                    const float* q = KS + (nt * 8 + g) * 36 + ck + t;
                    unsigned bh[2], br[2];
                    tf32_split(q[0], bh[0], br[0]);
                    tf32_split(q[4], bh[1], br[1]);
                    mma_tf32(s_[nt], ar, bh);
                    mma_tf32(s_[nt], ah, br);
                    mma_tf32(s_[nt], ah, bh);
                }
            }

            // bias + softmax
            const float* bh_tab = bias_tab + hg * (N_TOK * N_TOK);
            const int r0 = wr * 16 + g;
#pragma unroll
            for (int nt = 0; nt < 8; nt++) {
                const int c = nt * 8 + 2 * t;
                float2 b0 = *(const float2*)&bh_tab[r0 * 64 + c];
                float2 b1 = *(const float2*)&bh_tab[(r0 + 8) * 64 + c];
                s_[nt][0] += b0.x;  s_[nt][1] += b0.y;
                s_[nt][2] += b1.x;  s_[nt][3] += b1.y;
            }
            float m0 = -1e30f, m1 = -1e30f;
#pragma unroll
            for (int nt = 0; nt < 8; nt++) {
                m0 = fmaxf(m0, fmaxf(s_[nt][0], s_[nt][1]));
                m1 = fmaxf(m1, fmaxf(s_[nt][2], s_[nt][3]));
            }
            m0 = fmaxf(m0, __shfl_xor_sync(0xffffffffu, m0, 1));
            m0 = fmaxf(m0, __shfl_xor_sync(0xffffffffu, m0, 2));
            m1 = fmaxf(m1, __shfl_xor_sync(0xffffffffu, m1, 1));
            m1 = fmaxf(m1, __shfl_xor_sync(0xffffffffu, m1, 2));
            float s0 = 0.0f, s1 = 0.0f;
#pragma unroll
            for (int nt = 0; nt < 8; nt++) {
                s_[nt][0] = __expf(s_[nt][0] - m0);
                s_[nt][1] = __expf(s_[nt][1] - m0);
                s_[nt][2] = __expf(s_[nt][2] - m1);
                s_[nt][3] = __expf(s_[nt][3] - m1);
                s0 += s_[nt][0] + s_[nt][1];
                s1 += s_[nt][2] + s_[nt][3];
            }
            s0 += __shfl_xor_sync(0xffffffffu, s0, 1);
            s0 += __shfl_xor_sync(0xffffffffu, s0, 2);
            s1 += __shfl_xor_sync(0xffffffffu, s1, 1);
            s1 += __shfl_xor_sync(0xffffffffu, s1, 2);
            const float i0 = __frcp_rn(s0), i1 = __frcp_rn(s1);
#pragma unroll
            for (int nt = 0; nt < 8; nt++) {
                s_[nt][0] *= i0;  s_[nt][1] *= i0;
                s_[nt][2] *= i1;  s_[nt][3] *= i1;
            }
        }
        __syncthreads();   // all Q/K reads done before P overwrites

        if (warp < 8) {
            const int r0 = wr * 16 + g;
#pragma unroll
            for (int nt = 0; nt < 8; nt++) {
                const int c = nt * 8 + 2 * t;
                *(float2*)&PS[r0 * PS_STRIDE + c]       = make_float2(s_[nt][0], s_[nt][1]);
                *(float2*)&PS[(r0 + 8) * PS_STRIDE + c] = make_float2(s_[nt][2], s_[nt][3]);
            }
        }
        __syncthreads();   // P visible

        if (warp < 8) {
            float o[4][4];
#pragma unroll
            for (int nt = 0; nt < 4; nt++)
#pragma unroll
                for (int r = 0; r < 4; r++) o[nt][r] = 0.0f;

#pragma unroll
            for (int ks = 0; ks < 8; ++ks) {
                const int ck = ks * 8;
                unsigned ah[4], ar[4];
                const float* p = PS + (wr * 16 + g) * PS_STRIDE + ck + t;
                tf32_split(p[0],                 ah[0], ar[0]);
                tf32_split(p[8 * PS_STRIDE],     ah[1], ar[1]);
                tf32_split(p[4],                 ah[2], ar[2]);
                tf32_split(p[8 * PS_STRIDE + 4], ah[3], ar[3]);
#pragma unroll
                for (int nt = 0; nt < 4; nt++) {
                    const float* q = VS + (ck + t) * 36 + nt * 8 + g;
                    unsigned bh[2], br[2];
                    tf32_split(q[0],      bh[0], br[0]);
                    tf32_split(q[4 * 36], bh[1], br[1]);
                    mma_tf32(o[nt], ar, bh);
                    mma_tf32(o[nt], ah, br);
                    mma_tf32(o[nt], ah, bh);
                }
            }

            // O -> AO bf16 hi/res planes
            unsigned short* AOhi  = smu + AO_BASE_S;
            unsigned short* AOres = AOhi + AO_PLANE;
            const int r0 = wr * 16 + g;
#pragma unroll
            for (int nt = 0; nt < 4; nt++) {
                const int col = hg * HDIM + nt * 8 + 2 * t;
                unsigned hi, res;
                bf16_split_pack(o[nt][0], o[nt][1], hi, res);
                *(unsigned*)&AOhi [r0 * AO_STRIDE + col] = hi;
                *(unsigned*)&AOres[r0 * AO_STRIDE + col] = res;
                bf16_split_pack(o[nt][2], o[nt][3], hi, res);
                *(unsigned*)&AOhi [(r0 + 8) * AO_STRIDE + col] = hi;
                *(unsigned*)&AOres[(r0 + 8) * AO_STRIDE + col] = res;
            }
        }
        __syncthreads();   // QKV region free for next hp
    }

    // ================= phase 3: out-proj =================
    unsigned short* AOhi  = smu + AO_BASE_S;
    unsigned short* AOres = AOhi + AO_PLANE;
    unsigned short* WPbuf = smu;               // aliases dead A+B bufs

    auto issue_wp = [&](int kt, int buf) {
        unsigned short* bh = WPbuf + buf * WP_BUF;
        unsigned short* br = bh + WP_PLANE;
        const int ko = kt * 32;
#pragma unroll
        for (int i = 0; i < 2; i++) {
            int j = tid + 512 * i;                 // 0..1023
            const int row = j >> 2, ch = (j & 3) * 8;
            cp_async16(&bh[row * TPAD + ch], WPhi  + row * 256 + ko + ch);
            cp_async16(&br[row * TPAD + ch], WPres + row * 256 + ko + ch);
        }
        asm volatile("cp.async.commit_group;\n");
    };

    issue_wp(0, 0);

    float oc[2][4][4];
#pragma unroll
    for (int mt = 0; mt < 2; mt++)
#pragma unroll
        for (int nt = 0; nt < 4; nt++)
#pragma unroll
            for (int r = 0; r < 4; r++) oc[mt][nt][r] = 0.0f;

    for (int kt = 0; kt < 8; ++kt) {
        asm volatile("cp.async.wait_group 0;\n" ::: "memory");
        __syncthreads();
        if (kt + 1 < 8) issue_wp(kt + 1, (kt + 1) & 1);

        const unsigned short* Bh = WPbuf + (kt & 1) * WP_BUF;
        const unsigned short* Br = Bh + WP_PLANE;

#pragma unroll
        for (int ks = 0; ks < 2; ++ks) {
            const int ck = kt * 32 + ks * 16;      // A col
            const int bk = ks * 16;                // B col
            unsigned bh[4][2], br[4][2];
#pragma unroll
            for (int nt = 0; nt < 4; nt++) {
                const int boff = (wn * 32 + nt * 8 + lb_row) * TPAD + bk + lb_col;
                ldsm_x2(bh[nt], Bh + boff);
                ldsm_x2(br[nt], Br + boff);
            }
#pragma unroll
            for (int mt = 0; mt < 2; mt++) {
                const int aoff = (wm2 * 32 + mt * 16 + la_row) * AO_STRIDE + ck + la_col;
                unsigned ah[4], ar[4];
                ldsm_x4(ah, AOhi  + aoff);
                ldsm_x4(ar, AOres + aoff);
#pragma unroll
                for (int nt = 0; nt < 4; nt++) {
                    mma_bf16(oc[mt][nt], ar, bh[nt]);
                    mma_bf16(oc[mt][nt], ah, br[nt]);
                    mma_bf16(oc[mt][nt], ah, bh[nt]);
                }
            }
        }
        __syncthreads();
    }

#pragma unroll
    for (int mt = 0; mt < 2; mt++) {
        const int r0 = wm2 * 32 + mt * 16 + g;
#pragma unroll
        for (int nt = 0; nt < 4; nt++) {
            const int col = wn * 32 + nt * 8 + 2 * t;
            const float b0 = bp[col], b1 = bp[col + 1];
            float* op0 = out + ((size_t)b * N_TOK + r0)     * DIM_C + col;
            float* op1 = out + ((size_t)b * N_TOK + r0 + 8) * DIM_C + col;
            *(float2*)op0 = make_float2(oc[mt][nt][0] + b0, oc[mt][nt][1] + b1);
            *(float2*)op1 = make_float2(oc[mt][nt][2] + b0, oc[mt][nt][3] + b1);
        }
    }
}

// ---------------------------------------------------------------------------
extern "C" void kernel_launch(void* const* d_in, const int* in_sizes, int n_in,
                              void* d_out, int out_size)
{
    const float* x      = (const float*)d_in[0];
    const float* wq     = (const float*)d_in[1];
    const float* bq     = (const float*)d_in[2];
    const float* wkv    = (const float*)d_in[3];
    const float* bkv    = (const float*)d_in[4];
    const float* wp     = (const float*)d_in[5];
    const float* bp     = (const float*)d_in[6];
    const float* rpb    = (const float*)d_in[7];
    const int*   relidx = (const int*)  d_in[8];
    float* out = (float*)d_out;

    float *bqkv = nullptr, *bias = nullptr;
    unsigned short *wthi, *wtres, *wpthi, *wptres;
    cudaGetSymbolAddress((void**)&bqkv,   g_bqkv);
    cudaGetSymbolAddress((void**)&bias,   g_bias);
    cudaGetSymbolAddress((void**)&wthi,   g_wthi);
    cudaGetSymbolAddress((void**)&wtres,  g_wtres);
    cudaGetSymbolAddress((void**)&wpthi,  g_wpthi);
    cudaGetSymbolAddress((void**)&wptres, g_wptres);

    cudaFuncSetAttribute(fused_all, cudaFuncAttributeMaxDynamicSharedMemorySize,
                         FUSED_SMEM);

    pack_w<<<(QKV_LD * DIM_C + 255) / 256, 256>>>(wq, bq, wkv, bkv, wp, rpb, relidx);

    fused_all<<<B_WIN, 512, FUSED_SMEM>>>(x, bias, wthi, wtres, bqkv,
                                          wpthi, wptres, bp, out);
}

// round 12
// speedup vs baseline: 1.0954x; 1.0954x over previous
#include <cuda_runtime.h>
#include <cuda_bf16.h>
#include <cstdint>

// ---------------------------------------------------------------------------
// TotalAttention, r10 structure + bf16x3 attention:
//   0) pack_w: wq(*scale)|wkv -> split planes [768][256]; wp planes; biases;
//      bias table
//   1) gemm_qkv: qkv = x @ wqkv + b (3xBF16, in-kernel A split) ->
//      qkv stored as bf16 hi/res planes [M][768] (split in epilogue)
//   2) attn_fused: per window (512 thr):
//      - load q/k/v planes into swizzled smem (SW64, 64B rows)
//      - QK^T via 3xBF16 mma (ldsm) + bias + softmax (regs)
//      - P split -> SW128 planes; PV via 3xBF16 (A=P ldsm, B=V ldsm.trans)
//      - in-block out-proj (3xBF16, wp streamed) -> d_out
// ---------------------------------------------------------------------------

#define B_WIN   4096
#define N_TOK   64
#define DIM_C   256
#define HEADS   8
#define HDIM    32
#define M_ROWS  (B_WIN * N_TOK)
#define QKV_LD  768
#define SCALE_F 0.17677669529663687f

__device__ unsigned short g_qkvhi [(size_t)M_ROWS * QKV_LD];  // 402 MB
__device__ unsigned short g_qkvres[(size_t)M_ROWS * QKV_LD];  // 402 MB
__device__ unsigned short g_wthi [QKV_LD * DIM_C];
__device__ unsigned short g_wtres[QKV_LD * DIM_C];
__device__ unsigned short g_wpthi [DIM_C * DIM_C];
__device__ unsigned short g_wptres[DIM_C * DIM_C];
__device__ float g_bqkv[QKV_LD];
__device__ float g_bias[HEADS * N_TOK * N_TOK];

// ---------------------------------------------------------------------------
__device__ __forceinline__ void cp_async16(void* smem_dst, const void* gsrc) {
    unsigned saddr = (unsigned)__cvta_generic_to_shared(smem_dst);
    asm volatile("cp.async.cg.shared.global [%0], [%1], 16;\n"
                 :: "r"(saddr), "l"(gsrc));
}

__device__ __forceinline__ void ldsm_x4(unsigned* r, const void* p) {
    unsigned a = (unsigned)__cvta_generic_to_shared(p);
    asm volatile("ldmatrix.sync.aligned.m8n8.x4.shared.b16 {%0,%1,%2,%3}, [%4];"
                 : "=r"(r[0]), "=r"(r[1]), "=r"(r[2]), "=r"(r[3]) : "r"(a));
}

__device__ __forceinline__ void ldsm_x2(unsigned* r, const void* p) {
    unsigned a = (unsigned)__cvta_generic_to_shared(p);
    asm volatile("ldmatrix.sync.aligned.m8n8.x2.shared.b16 {%0,%1}, [%2];"
                 : "=r"(r[0]), "=r"(r[1]) : "r"(a));
}

__device__ __forceinline__ void ldsm_x2_trans(unsigned* r, const void* p) {
    unsigned a = (unsigned)__cvta_generic_to_shared(p);
    asm volatile("ldmatrix.sync.aligned.m8n8.x2.trans.shared.b16 {%0,%1}, [%2];"
                 : "=r"(r[0]), "=r"(r[1]) : "r"(a));
}

__device__ __forceinline__ void mma_bf16(float* c, const unsigned* a, const unsigned* b) {
    asm volatile(
        "mma.sync.aligned.m16n8k16.row.col.f32.bf16.bf16.f32 "
        "{%0,%1,%2,%3}, {%4,%5,%6,%7}, {%8,%9}, {%0,%1,%2,%3};\n"
        : "+f"(c[0]), "+f"(c[1]), "+f"(c[2]), "+f"(c[3])
        : "r"(a[0]), "r"(a[1]), "r"(a[2]), "r"(a[3]),
          "r"(b[0]), "r"(b[1]));
}

__device__ __forceinline__ void bf16_split(float f, unsigned short& hi, unsigned short& res) {
    __nv_bfloat16 h = __float2bfloat16_rn(f);
    float r = f - __bfloat162float(h);
    hi  = __bfloat16_as_ushort(h);
    res = __bfloat16_as_ushort(__float2bfloat16_rn(r));
}

__device__ __forceinline__ void bf16_split_pack(float a, float b, unsigned& hi, unsigned& res) {
    unsigned short ha, ra, hb, rb;
    bf16_split(a, ha, ra);
    bf16_split(b, hb, rb);
    hi  = (unsigned)ha | ((unsigned)hb << 16);
    res = (unsigned)ra | ((unsigned)rb << 16);
}

__device__ __forceinline__ uint32_t swz64(uint32_t off)  { return off ^ ((off >> 3) & 0x30); }
__device__ __forceinline__ uint32_t swz128(uint32_t off) { return off ^ ((off >> 3) & 0x70); }

// ---------------------------------------------------------------------------
__global__ void pack_w(const float* __restrict__ wq, const float* __restrict__ bq,
                       const float* __restrict__ wkv, const float* __restrict__ bkv,
                       const float* __restrict__ wp,
                       const float* __restrict__ rpb, const int* __restrict__ relidx)
{
    int i = blockIdx.x * blockDim.x + threadIdx.x;
    if (i < QKV_LD * DIM_C) {
        int n = i / DIM_C, k = i % DIM_C;
        float v = (n < DIM_C) ? wq[k * DIM_C + n] * SCALE_F
                              : wkv[k * 512 + (n - DIM_C)];
        bf16_split(v, g_wthi[i], g_wtres[i]);
    }
    if (i < DIM_C * DIM_C) {
        int n = i / DIM_C, k = i % DIM_C;
        bf16_split(wp[k * DIM_C + n], g_wpthi[i], g_wptres[i]);
    }
    if (i < QKV_LD) g_bqkv[i] = (i < DIM_C) ? bq[i] * SCALE_F : bkv[i - DIM_C];
    if (i < HEADS * N_TOK * N_TOK) {
        int h = i >> 12, nm = i & 4095;
        g_bias[i] = rpb[relidx[nm] * HEADS + h];
    }
}

// ---------------------------------------------------------------------------
// qkv GEMM (r10 verbatim except epilogue: split-stores into hi/res planes)
// ---------------------------------------------------------------------------
#define TPAD 40
#define APLANE (128 * TPAD)
#define ABUF   (2 * APLANE)
#define BBASE  (2 * ABUF)
#define GEMM_SMEM (4 * ABUF * 2)        // 81920 bytes

__global__ __launch_bounds__(256, 2)
void gemm_qkv(const float* __restrict__ X,
              const unsigned short* __restrict__ Bhi_g,
              const unsigned short* __restrict__ Bres_g,
              const float* __restrict__ bias,
              unsigned short* __restrict__ Chi,
              unsigned short* __restrict__ Cres)
{
    extern __shared__ __align__(16) unsigned short smu[];

    const int tid  = threadIdx.x;
    const int warp = tid >> 5, lane = tid & 31;
    const int wm = warp >> 2, wn = warp & 3;
    const int g  = lane >> 2, t  = lane & 3;
    const size_t n0 = (size_t)blockIdx.x * 128;
    const size_t m0 = (size_t)blockIdx.y * 128;

    const int c0   = tid * 2;
    const int brow0 = c0 >> 2, bcc0 = (c0 & 3) * 8;
    const int brow1 = (c0 + 1) >> 2, bcc1 = ((c0 + 1) & 3) * 8;

    int arow[4], acc_[4];
#pragma unroll
    for (int j = 0; j < 4; j++) {
        const int c = tid + 256 * j;
        arow[j] = c >> 3;
        acc_[j] = (c & 7) * 4;
    }

    const int la_row = lane & 15;
    const int la_col = (lane >> 4) * 8;
    const int lb_row = lane & 7;
    const int lb_col = ((lane >> 3) & 1) * 8;

    float acc[4][4][4];
#pragma unroll
    for (int mt = 0; mt < 4; mt++)
#pragma unroll
        for (int nt = 0; nt < 4; nt++)
#pragma unroll
            for (int r = 0; r < 4; r++) acc[mt][nt][r] = 0.0f;

    auto issue_B = [&](int kt, int buf) {
        unsigned short* bh = smu + BBASE + buf * ABUF;
        unsigned short* br = bh + APLANE;
        const int ko = kt * 32;
        cp_async16(&bh[brow0 * TPAD + bcc0], Bhi_g  + (n0 + brow0) * 256 + ko + bcc0);
        cp_async16(&bh[brow1 * TPAD + bcc1], Bhi_g  + (n0 + brow1) * 256 + ko + bcc1);
        cp_async16(&br[brow0 * TPAD + bcc0], Bres_g + (n0 + brow0) * 256 + ko + bcc0);
        cp_async16(&br[brow1 * TPAD + bcc1], Bres_g + (n0 + brow1) * 256 + ko + bcc1);
        asm volatile("cp.async.commit_group;\n");
    };

    auto load_A = [&](int kt, float4* regs) {
        const int ko = kt * 32;
#pragma unroll
        for (int j = 0; j < 4; j++)
            regs[j] = *(const float4*)(X + (m0 + arow[j]) * 256 + ko + acc_[j]);
    };

    float4 aReg[4];
    load_A(0, aReg);
    issue_B(0, 0);

    for (int kt = 0; kt < 8; ++kt) {
        asm volatile("cp.async.wait_group 0;\n" ::: "memory");

        {
            unsigned short* ah = smu + (kt & 1) * ABUF;
            unsigned short* ar = ah + APLANE;
#pragma unroll
            for (int j = 0; j < 4; j++) {
                unsigned h0, r0w, h1, r1w;
                bf16_split_pack(aReg[j].x, aReg[j].y, h0, r0w);
                bf16_split_pack(aReg[j].z, aReg[j].w, h1, r1w);
                const int off = arow[j] * TPAD + acc_[j];
                *(unsigned long long*)&ah[off] =
                    (unsigned long long)h0 | ((unsigned long long)h1 << 32);
                *(unsigned long long*)&ar[off] =
                    (unsigned long long)r0w | ((unsigned long long)r1w << 32);
            }
        }
        __syncthreads();

        if (kt + 1 < 8) {
            load_A(kt + 1, aReg);
            issue_B(kt + 1, (kt + 1) & 1);
        }

        const unsigned short* As_hi  = smu + (kt & 1) * ABUF;
        const unsigned short* As_res = As_hi + APLANE;
        const unsigned short* Bs_hi  = smu + BBASE + (kt & 1) * ABUF;
        const unsigned short* Bs_res = Bs_hi + APLANE;

#pragma unroll
        for (int ks = 0; ks < 2; ++ks) {
            const int ck = ks * 16;
            unsigned bh[4][2], br[4][2];
#pragma unroll
            for (int nt = 0; nt < 4; nt++) {
                const int boff = (wn * 32 + nt * 8 + lb_row) * TPAD + ck + lb_col;
                ldsm_x2(bh[nt], Bs_hi  + boff);
                ldsm_x2(br[nt], Bs_res + boff);
            }
#pragma unroll
            for (int mt = 0; mt < 4; mt++) {
                const int aoff = (wm * 64 + mt * 16 + la_row) * TPAD + ck + la_col;
                unsigned ah[4], ar[4];
                ldsm_x4(ah, As_hi  + aoff);
                ldsm_x4(ar, As_res + aoff);
#pragma unroll
                for (int nt = 0; nt < 4; nt++) {
                    mma_bf16(acc[mt][nt], ar, bh[nt]);
                    mma_bf16(acc[mt][nt], ah, br[nt]);
                    mma_bf16(acc[mt][nt], ah, bh[nt]);
                }
            }
        }
        __syncthreads();
    }

    // epilogue: bias + bf16 split stores
#pragma unroll
    for (int mt = 0; mt < 4; mt++) {
        const size_t r0 = m0 + wm * 64 + mt * 16 + g;
#pragma unroll
        for (int nt = 0; nt < 4; nt++) {
            const size_t col = n0 + wn * 32 + nt * 8 + 2 * t;
            const float b0 = bias[col], b1 = bias[col + 1];
            const size_t e0 = r0 * QKV_LD + col;
            const size_t e1 = (r0 + 8) * QKV_LD + col;
            unsigned hi, res;
            bf16_split_pack(acc[mt][nt][0] + b0, acc[mt][nt][1] + b1, hi, res);
            ((unsigned*)Chi)[e0 >> 1]  = hi;
            ((unsigned*)Cres)[e0 >> 1] = res;
            bf16_split_pack(acc[mt][nt][2] + b0, acc[mt][nt][3] + b1, hi, res);
            ((unsigned*)Chi)[e1 >> 1]  = hi;
            ((unsigned*)Cres)[e1 >> 1] = res;
        }
    }
}

// ---------------------------------------------------------------------------
// Attention (bf16x3, ldsm) + fused out-proj. Block = window, 512 threads.
// Smem (shorts): per head h (base h*12288):
//   Qhi [0,2048) Qres [2048,4096) Khi [4096,6144) Kres [6144,8192)
//   Vhi [8192,10240) Vres [10240,12288)
//   Q/K/V rows = 64B (32 shorts), SW64 swizzle.
//   P planes alias Q+K: Phi [0,4096), Pres [4096,8192); rows 128B, SW128.
// Phase 3: AO planes at base (stride 264), wp bufs after (r10 verbatim).
// ---------------------------------------------------------------------------
#define HEAD_S  12288
#define AO_STRIDE 264
#define AO_PLANE  (64 * AO_STRIDE)
#define WP_PLANE  (256 * TPAD)
#define WP_BUF    (2 * WP_PLANE)
#define ATTN_SMEM (8 * HEAD_S * 2)     // 196608 bytes

__global__ __launch_bounds__(512, 1)
void attn_fused(const unsigned short* __restrict__ qhi,
                const unsigned short* __restrict__ qres,
                const float* __restrict__ bias,
                const unsigned short* __restrict__ WPhi,
                const unsigned short* __restrict__ WPres,
                const float* __restrict__ bp,
                float* __restrict__ out)
{
    extern __shared__ __align__(16) unsigned short smu[];
    const int b    = blockIdx.x;
    const int tid  = threadIdx.x;
    const int warp = tid >> 5;
    const int lane = tid & 31;
    const int h    = warp >> 1;
    const int half = warp & 1;
    const int g = lane >> 2, t = lane & 3;

    const int la_row = lane & 15, la_col = (lane >> 4) * 8;
    const int lb_row = lane & 7,  lb_col = ((lane >> 3) & 1) * 8;

    // ---- load q/k/v planes into swizzled smem ----
    const size_t gbase = (size_t)b * 64 * QKV_LD;
    for (int i = tid; i < 12288; i += 512) {
        const int ch  = i & 3;
        const int row = (i >> 2) & 63;
        const int tt  = i >> 8;            // 0..47
        const int p   = tt & 1;
        const int hr  = tt >> 1;           // 0..23
        const int r   = hr % 3;
        const int hh  = hr / 3;
        const unsigned short* gp = (p ? qres : qhi) + gbase + row * QKV_LD
                                   + r * 256 + hh * 32 + ch * 8;
        char* sbase = (char*)(smu + hh * HEAD_S + r * 4096 + p * 2048);
        cp_async16(sbase + swz64(row * 64 + ch * 16), gp);
    }
    asm volatile("cp.async.commit_group;\n");
    asm volatile("cp.async.wait_group 0;\n" ::: "memory");
    __syncthreads();

    const char* Qhi  = (const char*)(smu + h * HEAD_S);
    const char* Qres = Qhi + 4096;
    const char* Khi  = Qhi + 8192;
    const char* Kres = Qhi + 12288;
    const char* Vhi  = Qhi + 16384;
    const char* Vres = Qhi + 20480;
    char* Phi  = (char*)(smu + h * HEAD_S);          // aliases Q
    char* Pres = Phi + 8192;                          // aliases K

    // ---- S = Q @ K^T (3xBF16, K=32 -> 2 kt) ----
    float s_[2][8][4];
#pragma unroll
    for (int mt = 0; mt < 2; mt++)
#pragma unroll
        for (int nt = 0; nt < 8; nt++)
#pragma unroll
            for (int r = 0; r < 4; r++) s_[mt][nt][r] = 0.0f;

#pragma unroll
    for (int kt = 0; kt < 2; ++kt) {
        unsigned bh[8][2], br[8][2];
#pragma unroll
        for (int nt = 0; nt < 8; nt++) {
            const uint32_t boff = swz64((nt * 8 + lb_row) * 64 + kt * 32 + lb_col * 2);
            ldsm_x2(bh[nt], Khi  + boff);
            ldsm_x2(br[nt], Kres + boff);
        }
#pragma unroll
        for (int mt = 0; mt < 2; mt++) {
            const uint32_t aoff =
                swz64((half * 32 + mt * 16 + la_row) * 64 + kt * 32 + la_col * 2);
            unsigned ah[4], ar[4];
            ldsm_x4(ah, Qhi  + aoff);
            ldsm_x4(ar, Qres + aoff);
#pragma unroll
            for (int nt = 0; nt < 8; nt++) {
                mma_bf16(s_[mt][nt], ar, bh[nt]);
                mma_bf16(s_[mt][nt], ah, br[nt]);
                mma_bf16(s_[mt][nt], ah, bh[nt]);
            }
        }
    }

    // ---- bias + softmax (regs, r10 verbatim) ----
    const float* bh_tab = bias + h * (N_TOK * N_TOK);
#pragma unroll
    for (int mt = 0; mt < 2; mt++) {
        const int r0 = half * 32 + mt * 16 + g;
#pragma unroll
        for (int nt = 0; nt < 8; nt++) {
            const int c = nt * 8 + 2 * t;
            float2 b0 = *(const float2*)&bh_tab[r0 * 64 + c];
            float2 b1 = *(const float2*)&bh_tab[(r0 + 8) * 64 + c];
            s_[mt][nt][0] += b0.x;  s_[mt][nt][1] += b0.y;
            s_[mt][nt][2] += b1.x;  s_[mt][nt][3] += b1.y;
        }
    }
#pragma unroll
    for (int mt = 0; mt < 2; mt++) {
        float m0 = -1e30f, m1 = -1e30f;
#pragma unroll
        for (int nt = 0; nt < 8; nt++) {
            m0 = fmaxf(m0, fmaxf(s_[mt][nt][0], s_[mt][nt][1]));
            m1 = fmaxf(m1, fmaxf(s_[mt][nt][2], s_[mt][nt][3]));
        }
        m0 = fmaxf(m0, __shfl_xor_sync(0xffffffffu, m0, 1));
        m0 = fmaxf(m0, __shfl_xor_sync(0xffffffffu, m0, 2));
        m1 = fmaxf(m1, __shfl_xor_sync(0xffffffffu, m1, 1));
        m1 = fmaxf(m1, __shfl_xor_sync(0xffffffffu, m1, 2));
        float s0 = 0.0f, s1 = 0.0f;
#pragma unroll
        for (int nt = 0; nt < 8; nt++) {
            s_[mt][nt][0] = __expf(s_[mt][nt][0] - m0);
            s_[mt][nt][1] = __expf(s_[mt][nt][1] - m0);
            s_[mt][nt][2] = __expf(s_[mt][nt][2] - m1);
            s_[mt][nt][3] = __expf(s_[mt][nt][3] - m1);
            s0 += s_[mt][nt][0] + s_[mt][nt][1];
            s1 += s_[mt][nt][2] + s_[mt][nt][3];
        }
        s0 += __shfl_xor_sync(0xffffffffu, s0, 1);
        s0 += __shfl_xor_sync(0xffffffffu, s0, 2);
        s1 += __shfl_xor_sync(0xffffffffu, s1, 1);
        s1 += __shfl_xor_sync(0xffffffffu, s1, 2);
        const float i0 = __frcp_rn(s0), i1 = __frcp_rn(s1);
#pragma unroll
        for (int nt = 0; nt < 8; nt++) {
            s_[mt][nt][0] *= i0;  s_[mt][nt][1] *= i0;
            s_[mt][nt][2] *= i1;  s_[mt][nt][3] *= i1;
        }
    }

    asm volatile("bar.sync %0, %1;" :: "r"(1 + h), "r"(64) : "memory");

    // ---- P split -> SW128 planes ----
#pragma unroll
    for (int mt = 0; mt < 2; mt++) {
        const int r0 = half * 32 + mt * 16 + g;
#pragma unroll
        for (int nt = 0; nt < 8; nt++) {
            const int c = nt * 8 + 2 * t;
            unsigned hi, res;
            bf16_split_pack(s_[mt][nt][0], s_[mt][nt][1], hi, res);
            const uint32_t o0 = swz128(r0 * 128 + c * 2);
            *(unsigned*)(Phi + o0)  = hi;
            *(unsigned*)(Pres + o0) = res;
            bf16_split_pack(s_[mt][nt][2], s_[mt][nt][3], hi, res);
            const uint32_t o1 = swz128((r0 + 8) * 128 + c * 2);
            *(unsigned*)(Phi + o1)  = hi;
            *(unsigned*)(Pres + o1) = res;
        }
    }
    asm volatile("bar.sync %0, %1;" :: "r"(1 + h), "r"(64) : "memory");

    // ---- O = P @ V (3xBF16, K=64 -> 4 kt); V B-frags via ldsm.trans ----
    float o[2][4][4];
#pragma unroll
    for (int mt = 0; mt < 2; mt++)
#pragma unroll
        for (int nt = 0; nt < 4; nt++)
#pragma unroll
            for (int r = 0; r < 4; r++) o[mt][nt][r] = 0.0f;

#pragma unroll
    for (int kt = 0; kt < 4; ++kt) {
        unsigned bh[4][2], br[4][2];
#pragma unroll
        for (int nt = 0; nt < 4; nt++) {
            // trans: lanes 0-15 -> k-rows kt*16+(lane&15); col chunk nt*16 B
            const uint32_t boff = swz64((kt * 16 + (lane & 15)) * 64 + nt * 16);
            ldsm_x2_trans(bh[nt], Vhi  + boff);
            ldsm_x2_trans(br[nt], Vres + boff);
        }
#pragma unroll
        for (int mt = 0; mt < 2; mt++) {
            const uint32_t aoff =
                swz128((half * 32 + mt * 16 + la_row) * 128 + kt * 32 + la_col * 2);
            unsigned ah[4], ar[4];
            ldsm_x4(ah, Phi  + aoff);
            ldsm_x4(ar, Pres + aoff);
#pragma unroll
            for (int nt = 0; nt < 4; nt++) {
                mma_bf16(o[mt][nt], ar, bh[nt]);
                mma_bf16(o[mt][nt], ah, br[nt]);
                mma_bf16(o[mt][nt], ah, bh[nt]);
            }
        }
    }

    // ============ phase 2: fused out-proj (r10 verbatim) ============
    __syncthreads();

    unsigned short* AOhi  = smu;
    unsigned short* AOres = AOhi + AO_PLANE;
    unsigned short* WPbuf = AOres + AO_PLANE;

#pragma unroll
    for (int mt = 0; mt < 2; mt++) {
        const int r0 = half * 32 + mt * 16 + g;
#pragma unroll
        for (int nt = 0; nt < 4; nt++) {
            const int col = h * HDIM + nt * 8 + 2 * t;
            unsigned hi, res;
            bf16_split_pack(o[mt][nt][0], o[mt][nt][1], hi, res);
            *(unsigned*)&AOhi [r0 * AO_STRIDE + col] = hi;
            *(unsigned*)&AOres[r0 * AO_STRIDE + col] = res;
            bf16_split_pack(o[mt][nt][2], o[mt][nt][3], hi, res);
            *(unsigned*)&AOhi [(r0 + 8) * AO_STRIDE + col] = hi;
            *(unsigned*)&AOres[(r0 + 8) * AO_STRIDE + col] = res;
        }
    }

    auto issue_wp = [&](int kt, int buf) {
        unsigned short* bh = WPbuf + buf * WP_BUF;
        unsigned short* br = bh + WP_PLANE;
        const int ko = kt * 32;
#pragma unroll
        for (int i = 0; i < 2; i++) {
            int j = tid + 512 * i;
            const int row = j >> 2, ch = (j & 3) * 8;
            cp_async16(&bh[row * TPAD + ch], WPhi  + row * 256 + ko + ch);
            cp_async16(&br[row * TPAD + ch], WPres + row * 256 + ko + ch);
        }
        asm volatile("cp.async.commit_group;\n");
    };

    issue_wp(0, 0);
    __syncthreads();

    const int wm2 = warp >> 3;
    const int wn2 = warp & 7;

    float oc[2][4][4];
#pragma unroll
    for (int mt = 0; mt < 2; mt++)
#pragma unroll
        for (int nt = 0; nt < 4; nt++)
#pragma unroll
            for (int r = 0; r < 4; r++) oc[mt][nt][r] = 0.0f;

    for (int kt = 0; kt < 8; ++kt) {
        asm volatile("cp.async.wait_group 0;\n" ::: "memory");
        __syncthreads();
        if (kt + 1 < 8) issue_wp(kt + 1, (kt + 1) & 1);

        const unsigned short* Bh = WPbuf + (kt & 1) * WP_BUF;
        const unsigned short* Br = Bh + WP_PLANE;

#pragma unroll
        for (int ks = 0; ks < 2; ++ks) {
            const int ck = kt * 32 + ks * 16;
            const int bk = ks * 16;
            unsigned bh[4][2], br[4][2];
#pragma unroll
            for (int nt = 0; nt < 4; nt++) {
                const int boff = (wn2 * 32 + nt * 8 + lb_row) * TPAD + bk + lb_col;
                ldsm_x2(bh[nt], Bh + boff);
                ldsm_x2(br[nt], Br + boff);
            }
#pragma unroll
            for (int mt = 0; mt < 2; mt++) {
                const int aoff = (wm2 * 32 + mt * 16 + la_row) * AO_STRIDE + ck + la_col;
                unsigned ah[4], ar[4];
                ldsm_x4(ah, AOhi  + aoff);
                ldsm_x4(ar, AOres + aoff);
#pragma unroll
                for (int nt = 0; nt < 4; nt++) {
                    mma_bf16(oc[mt][nt], ar, bh[nt]);
                    mma_bf16(oc[mt][nt], ah, br[nt]);
                    mma_bf16(oc[mt][nt], ah, bh[nt]);
                }
            }
        }
        __syncthreads();
    }

#pragma unroll
    for (int mt = 0; mt < 2; mt++) {
        const int r0 = wm2 * 32 + mt * 16 + g;
#pragma unroll
        for (int nt = 0; nt < 4; nt++) {
            const int col = wn2 * 32 + nt * 8 + 2 * t;
            const float b0 = bp[col], b1 = bp[col + 1];
            float* op0 = out + ((size_t)b * N_TOK + r0)     * DIM_C + col;
            float* op1 = out + ((size_t)b * N_TOK + r0 + 8) * DIM_C + col;
            *(float2*)op0 = make_float2(oc[mt][nt][0] + b0, oc[mt][nt][1] + b1);
            *(float2*)op1 = make_float2(oc[mt][nt][2] + b0, oc[mt][nt][3] + b1);
        }
    }
}

// ---------------------------------------------------------------------------
extern "C" void kernel_launch(void* const* d_in, const int* in_sizes, int n_in,
                              void* d_out, int out_size)
{
    const float* x      = (const float*)d_in[0];
    const float* wq     = (const float*)d_in[1];
    const float* bq     = (const float*)d_in[2];
    const float* wkv    = (const float*)d_in[3];
    const float* bkv    = (const float*)d_in[4];
    const float* wp     = (const float*)d_in[5];
    const float* bp     = (const float*)d_in[6];
    const float* rpb    = (const float*)d_in[7];
    const int*   relidx = (const int*)  d_in[8];
    float* out = (float*)d_out;

    float *bqkv = nullptr, *bias = nullptr;
    unsigned short *qkvhi, *qkvres, *wthi, *wtres, *wpthi, *wptres;
    cudaGetSymbolAddress((void**)&bqkv,   g_bqkv);
    cudaGetSymbolAddress((void**)&bias,   g_bias);
    cudaGetSymbolAddress((void**)&qkvhi,  g_qkvhi);
    cudaGetSymbolAddress((void**)&qkvres, g_qkvres);
    cudaGetSymbolAddress((void**)&wthi,   g_wthi);
    cudaGetSymbolAddress((void**)&wtres,  g_wtres);
    cudaGetSymbolAddress((void**)&wpthi,  g_wpthi);
    cudaGetSymbolAddress((void**)&wptres, g_wptres);

    cudaFuncSetAttribute(gemm_qkv,   cudaFuncAttributeMaxDynamicSharedMemorySize, GEMM_SMEM);
    cudaFuncSetAttribute(attn_fused, cudaFuncAttributeMaxDynamicSharedMemorySize, ATTN_SMEM);

    pack_w<<<(QKV_LD * DIM_C + 255) / 256, 256>>>(wq, bq, wkv, bkv, wp, rpb, relidx);

    {
        dim3 grid(QKV_LD / 128, M_ROWS / 128);   // (6, 2048)
        gemm_qkv<<<grid, 256, GEMM_SMEM>>>(x, wthi, wtres, bqkv, qkvhi, qkvres);
    }
    attn_fused<<<B_WIN, 512, ATTN_SMEM>>>(qkvhi, qkvres, bias, wpthi, wptres, bp, out);
}

// round 13
// speedup vs baseline: 2.3776x; 2.1706x over previous
#include <cuda_runtime.h>
#include <cuda_fp16.h>
#include <cuda_bf16.h>
#include <cstdint>

// ---------------------------------------------------------------------------
// TotalAttention — single-precision FP16 tensor pipeline (r10 structure):
//   0) pack_w: wq(*scale)|wkv -> fp16 wqkv^T [768][256]; wp^T fp16; biases;
//      bias table g_bias[h][n][m]
//   1) gemm_qkv: qkv = x @ wqkv + bqkv  (A: fp32->fp16 in-kernel; B fp16
//      streamed; single m16n8k16 f16 MMA) -> qkv fp16 [M][768]
//   2) attn_fused per window (512 thr):
//      - q/k/v fp16 -> SW64 smem; QK^T (f16 mma, ldsm) + bias + softmax(fp32)
//      - P fp16 -> SW128 (aliases Q+K); PV (A=P ldsm, B=V ldsm.trans)
//      - fused out-proj (f16 mma, wp streamed) -> d_out fp32
// Precision: fp16-RN inputs, fp32 accumulate. Expected rel_err ~4-6e-4.
// ---------------------------------------------------------------------------

#define B_WIN   4096
#define N_TOK   64
#define DIM_C   256
#define HEADS   8
#define HDIM    32
#define M_ROWS  (B_WIN * N_TOK)
#define QKV_LD  768
#define SCALE_F 0.17677669529663687f

__device__ unsigned short g_qkvh[(size_t)M_ROWS * QKV_LD];   // fp16, 402 MB
__device__ unsigned short g_wth [QKV_LD * DIM_C];            // wqkv^T fp16
__device__ unsigned short g_wph [DIM_C * DIM_C];             // wp^T fp16
__device__ float g_bqkv[QKV_LD];
__device__ float g_bias[HEADS * N_TOK * N_TOK];

// ---------------------------------------------------------------------------
__device__ __forceinline__ void cp_async16(void* smem_dst, const void* gsrc) {
    unsigned saddr = (unsigned)__cvta_generic_to_shared(smem_dst);
    asm volatile("cp.async.cg.shared.global [%0], [%1], 16;\n"
                 :: "r"(saddr), "l"(gsrc));
}

__device__ __forceinline__ void ldsm_x4(unsigned* r, const void* p) {
    unsigned a = (unsigned)__cvta_generic_to_shared(p);
    asm volatile("ldmatrix.sync.aligned.m8n8.x4.shared.b16 {%0,%1,%2,%3}, [%4];"
                 : "=r"(r[0]), "=r"(r[1]), "=r"(r[2]), "=r"(r[3]) : "r"(a));
}

__device__ __forceinline__ void ldsm_x2(unsigned* r, const void* p) {
    unsigned a = (unsigned)__cvta_generic_to_shared(p);
    asm volatile("ldmatrix.sync.aligned.m8n8.x2.shared.b16 {%0,%1}, [%2];"
                 : "=r"(r[0]), "=r"(r[1]) : "r"(a));
}

__device__ __forceinline__ void ldsm_x2_trans(unsigned* r, const void* p) {
    unsigned a = (unsigned)__cvta_generic_to_shared(p);
    asm volatile("ldmatrix.sync.aligned.m8n8.x2.trans.shared.b16 {%0,%1}, [%2];"
                 : "=r"(r[0]), "=r"(r[1]) : "r"(a));
}

__device__ __forceinline__ void mma_f16(float* c, const unsigned* a, const unsigned* b) {
    asm volatile(
        "mma.sync.aligned.m16n8k16.row.col.f32.f16.f16.f32 "
        "{%0,%1,%2,%3}, {%4,%5,%6,%7}, {%8,%9}, {%0,%1,%2,%3};\n"
        : "+f"(c[0]), "+f"(c[1]), "+f"(c[2]), "+f"(c[3])
        : "r"(a[0]), "r"(a[1]), "r"(a[2]), "r"(a[3]),
          "r"(b[0]), "r"(b[1]));
}

__device__ __forceinline__ unsigned h2pack(float a, float b) {
    __half2 h = __float22half2_rn(make_float2(a, b));
    return *(unsigned*)&h;
}

__device__ __forceinline__ uint32_t swz64(uint32_t off)  { return off ^ ((off >> 3) & 0x30); }
__device__ __forceinline__ uint32_t swz128(uint32_t off) { return off ^ ((off >> 3) & 0x70); }

// ---------------------------------------------------------------------------
__global__ void pack_w(const float* __restrict__ wq, const float* __restrict__ bq,
                       const float* __restrict__ wkv, const float* __restrict__ bkv,
                       const float* __restrict__ wp,
                       const float* __restrict__ rpb, const int* __restrict__ relidx)
{
    int i = blockIdx.x * blockDim.x + threadIdx.x;
    if (i < QKV_LD * DIM_C) {                 // wqkv^T: [n=768][k=256]
        int n = i / DIM_C, k = i % DIM_C;
        float v = (n < DIM_C) ? wq[k * DIM_C + n] * SCALE_F
                              : wkv[k * 512 + (n - DIM_C)];
        __half h = __float2half_rn(v);
        g_wth[i] = *(unsigned short*)&h;
    }
    if (i < DIM_C * DIM_C) {                  // wp^T: [n=256][k=256]
        int n = i / DIM_C, k = i % DIM_C;
        __half h = __float2half_rn(wp[k * DIM_C + n]);
        g_wph[i] = *(unsigned short*)&h;
    }
    if (i < QKV_LD) g_bqkv[i] = (i < DIM_C) ? bq[i] * SCALE_F : bkv[i - DIM_C];
    if (i < HEADS * N_TOK * N_TOK) {
        int h = i >> 12, nm = i & 4095;
        g_bias[i] = rpb[relidx[nm] * HEADS + h];
    }
}

// ---------------------------------------------------------------------------
// qkv GEMM (fp16 single): C[m0..+128, n0..+128] = x @ W^T + bias -> fp16.
// BK=32, 8 kt. A: fp32 regs -> fp16 smem (stride 40 halfs). B: cp.async.
// ---------------------------------------------------------------------------
#define TPAD 40
#define APLANE (128 * TPAD)            // 5120 halfs per buffer
#define BBASE  (2 * APLANE)            // B bufs start (halfs)
#define GEMM_SMEM (4 * APLANE * 2)     // 40960 bytes

__global__ __launch_bounds__(256, 2)
void gemm_qkv(const float* __restrict__ X,
              const unsigned short* __restrict__ Bh_g,
              const float* __restrict__ bias,
              unsigned short* __restrict__ C)
{
    extern __shared__ __align__(16) unsigned short smu[];

    const int tid  = threadIdx.x;
    const int warp = tid >> 5, lane = tid & 31;
    const int wm = warp >> 2, wn = warp & 3;
    const int g  = lane >> 2, t  = lane & 3;
    const size_t n0 = (size_t)blockIdx.x * 128;   // n fastest (L2 x-reuse)
    const size_t m0 = (size_t)blockIdx.y * 128;

    // B cp.async: 512 chunks16B per slice, 2/thread
    const int j0 = tid * 2;
    const int brow0 = j0 >> 2, bcc0 = (j0 & 3) * 8;
    const int brow1 = (j0 + 1) >> 2, bcc1 = ((j0 + 1) & 3) * 8;

    // A fp32: 4 float4/thread
    int arow[4], acol[4];
#pragma unroll
    for (int j = 0; j < 4; j++) {
        const int c = tid + 256 * j;
        arow[j] = c >> 3;
        acol[j] = (c & 7) * 4;
    }

    const int la_row = lane & 15, la_col = (lane >> 4) * 8;
    const int lb_row = lane & 7,  lb_col = ((lane >> 3) & 1) * 8;

    float acc[4][4][4];
#pragma unroll
    for (int mt = 0; mt < 4; mt++)
#pragma unroll
        for (int nt = 0; nt < 4; nt++)
#pragma unroll
            for (int r = 0; r < 4; r++) acc[mt][nt][r] = 0.0f;

    auto issue_B = [&](int kt, int buf) {
        unsigned short* bh = smu + BBASE + buf * APLANE;
        const int ko = kt * 32;
        cp_async16(&bh[brow0 * TPAD + bcc0], Bh_g + (n0 + brow0) * 256 + ko + bcc0);
        cp_async16(&bh[brow1 * TPAD + bcc1], Bh_g + (n0 + brow1) * 256 + ko + bcc1);
        asm volatile("cp.async.commit_group;\n");
    };

    auto load_A = [&](int kt, float4* regs) {
        const int ko = kt * 32;
#pragma unroll
        for (int j = 0; j < 4; j++)
            regs[j] = *(const float4*)(X + (m0 + arow[j]) * 256 + ko + acol[j]);
    };

    float4 aReg[4];
    load_A(0, aReg);
    issue_B(0, 0);

    for (int kt = 0; kt < 8; ++kt) {
        asm volatile("cp.async.wait_group 0;\n" ::: "memory");

        // cvt + STS A slice into buffer kt&1
        {
            unsigned short* ah = smu + (kt & 1) * APLANE;
#pragma unroll
            for (int j = 0; j < 4; j++) {
                const unsigned p0 = h2pack(aReg[j].x, aReg[j].y);
                const unsigned p1 = h2pack(aReg[j].z, aReg[j].w);
                *(unsigned long long*)&ah[arow[j] * TPAD + acol[j]] =
                    (unsigned long long)p0 | ((unsigned long long)p1 << 32);
            }
        }
        __syncthreads();

        if (kt + 1 < 8) {
            load_A(kt + 1, aReg);
            issue_B(kt + 1, (kt + 1) & 1);
        }

        const unsigned short* As = smu + (kt & 1) * APLANE;
        const unsigned short* Bs = smu + BBASE + (kt & 1) * APLANE;

#pragma unroll
        for (int ks = 0; ks < 2; ++ks) {
            const int ck = ks * 16;
            unsigned bf[4][2];
#pragma unroll
            for (int nt = 0; nt < 4; nt++)
                ldsm_x2(bf[nt], Bs + (wn * 32 + nt * 8 + lb_row) * TPAD + ck + lb_col);
#pragma unroll
            for (int mt = 0; mt < 4; mt++) {
                unsigned af[4];
                ldsm_x4(af, As + (wm * 64 + mt * 16 + la_row) * TPAD + ck + la_col);
#pragma unroll
                for (int nt = 0; nt < 4; nt++)
                    mma_f16(acc[mt][nt], af, bf[nt]);
            }
        }
        __syncthreads();
    }

    // epilogue: bias + fp16 stores (half2 per row-pair, 16B/quad coalesced)
#pragma unroll
    for (int mt = 0; mt < 4; mt++) {
        const size_t r0 = m0 + wm * 64 + mt * 16 + g;
#pragma unroll
        for (int nt = 0; nt < 4; nt++) {
            const size_t col = n0 + wn * 32 + nt * 8 + 2 * t;
            const float b0 = bias[col], b1 = bias[col + 1];
            *(unsigned*)&C[r0 * QKV_LD + col] =
                h2pack(acc[mt][nt][0] + b0, acc[mt][nt][1] + b1);
            *(unsigned*)&C[(r0 + 8) * QKV_LD + col] =
                h2pack(acc[mt][nt][2] + b0, acc[mt][nt][3] + b1);
        }
    }
}

// ---------------------------------------------------------------------------
// Attention (fp16, ldsm) + fused out-proj. Block = window, 512 threads.
// Smem halfs: per head h (base h*6144):
//   Q [0,2048) | K [2048,4096) | V [4096,6144); rows 64B, SW64.
//   P aliases Q+K: [0,4096), rows 128B, SW128.
// Phase 3: AO (stride 264) at 0; wp bufs 2 x 10240 at 16896.
// ---------------------------------------------------------------------------
#define HEAD_H  6144
#define AO_STRIDE 264
#define AO_PLANE  (64 * AO_STRIDE)     // 16896 halfs
#define WP_PLANE  (256 * TPAD)         // 10240 halfs
#define ATTN_SMEM (8 * HEAD_H * 2)     // 98304 bytes

__global__ __launch_bounds__(512, 1)
void attn_fused(const unsigned short* __restrict__ qkvh,
                const float* __restrict__ bias,
                const unsigned short* __restrict__ WPh,
                const float* __restrict__ bp,
                float* __restrict__ out)
{
    extern __shared__ __align__(16) unsigned short smu[];
    const int b    = blockIdx.x;
    const int tid  = threadIdx.x;
    const int warp = tid >> 5, lane = tid & 31;
    const int h    = warp >> 1;
    const int half = warp & 1;
    const int g = lane >> 2, t = lane & 3;

    const int la_row = lane & 15, la_col = (lane >> 4) * 8;
    const int lb_row = lane & 7,  lb_col = ((lane >> 3) & 1) * 8;

    // ---- load q/k/v into SW64 smem (6144 chunks16B, 12/thread) ----
    const size_t gbase = (size_t)b * 64 * QKV_LD;
#pragma unroll
    for (int it = 0; it < 12; ++it) {
        const int i   = tid + it * 512;
        const int ch  = i & 3;
        const int row = (i >> 2) & 63;
        const int hr  = i >> 8;            // 0..23
        const int r   = hr % 3;
        const int hh  = hr / 3;
        const unsigned short* gp = qkvh + gbase + row * QKV_LD
                                   + r * 256 + hh * 32 + ch * 8;
        char* sb = (char*)(smu + hh * HEAD_H + r * 2048);
        cp_async16(sb + swz64(row * 64 + ch * 16), gp);
    }
    asm volatile("cp.async.commit_group;\n");
    asm volatile("cp.async.wait_group 0;\n" ::: "memory");
    __syncthreads();

    const char* Q = (const char*)(smu + h * HEAD_H);
    const char* K = Q + 4096;
    const char* V = Q + 8192;
    char* P = (char*)(smu + h * HEAD_H);       // aliases Q+K

    // ---- S = Q @ K^T (fp16 mma) ----
    float s_[2][8][4];
#pragma unroll
    for (int mt = 0; mt < 2; mt++)
#pragma unroll
        for (int nt = 0; nt < 8; nt++)
#pragma unroll
            for (int r = 0; r < 4; r++) s_[mt][nt][r] = 0.0f;

#pragma unroll
    for (int kt = 0; kt < 2; ++kt) {
        unsigned bf[8][2];
#pragma unroll
        for (int nt = 0; nt < 8; nt++)
            ldsm_x2(bf[nt], K + swz64((nt * 8 + lb_row) * 64 + kt * 32 + lb_col * 2));
#pragma unroll
        for (int mt = 0; mt < 2; mt++) {
            unsigned af[4];
            ldsm_x4(af, Q + swz64((half * 32 + mt * 16 + la_row) * 64 + kt * 32 + la_col * 2));
#pragma unroll
            for (int nt = 0; nt < 8; nt++)
                mma_f16(s_[mt][nt], af, bf[nt]);
        }
    }

    // ---- bias + softmax (fp32 regs) ----
    const float* bh_tab = bias + h * (N_TOK * N_TOK);
#pragma unroll
    for (int mt = 0; mt < 2; mt++) {
        const int r0 = half * 32 + mt * 16 + g;
#pragma unroll
        for (int nt = 0; nt < 8; nt++) {
            const int c = nt * 8 + 2 * t;
            float2 b0 = *(const float2*)&bh_tab[r0 * 64 + c];
            float2 b1 = *(const float2*)&bh_tab[(r0 + 8) * 64 + c];
            s_[mt][nt][0] += b0.x;  s_[mt][nt][1] += b0.y;
            s_[mt][nt][2] += b1.x;  s_[mt][nt][3] += b1.y;
        }
    }
#pragma unroll
    for (int mt = 0; mt < 2; mt++) {
        float m0 = -1e30f, m1 = -1e30f;
#pragma unroll
        for (int nt = 0; nt < 8; nt++) {
            m0 = fmaxf(m0, fmaxf(s_[mt][nt][0], s_[mt][nt][1]));
            m1 = fmaxf(m1, fmaxf(s_[mt][nt][2], s_[mt][nt][3]));
        }
        m0 = fmaxf(m0, __shfl_xor_sync(0xffffffffu, m0, 1));
        m0 = fmaxf(m0, __shfl_xor_sync(0xffffffffu, m0, 2));
        m1 = fmaxf(m1, __shfl_xor_sync(0xffffffffu, m1, 1));
        m1 = fmaxf(m1, __shfl_xor_sync(0xffffffffu, m1, 2));
        float s0 = 0.0f, s1 = 0.0f;
#pragma unroll
        for (int nt = 0; nt < 8; nt++) {
            s_[mt][nt][0] = __expf(s_[mt][nt][0] - m0);
            s_[mt][nt][1] = __expf(s_[mt][nt][1] - m0);
            s_[mt][nt][2] = __expf(s_[mt][nt][2] - m1);
            s_[mt][nt][3] = __expf(s_[mt][nt][3] - m1);
            s0 += s_[mt][nt][0] + s_[mt][nt][1];
            s1 += s_[mt][nt][2] + s_[mt][nt][3];
        }
        s0 += __shfl_xor_sync(0xffffffffu, s0, 1);
        s0 += __shfl_xor_sync(0xffffffffu, s0, 2);
        s1 += __shfl_xor_sync(0xffffffffu, s1, 1);
        s1 += __shfl_xor_sync(0xffffffffu, s1, 2);
        const float i0 = __frcp_rn(s0), i1 = __frcp_rn(s1);
#pragma unroll
        for (int nt = 0; nt < 8; nt++) {
            s_[mt][nt][0] *= i0;  s_[mt][nt][1] *= i0;
            s_[mt][nt][2] *= i1;  s_[mt][nt][3] *= i1;
        }
    }

    asm volatile("bar.sync %0, %1;" :: "r"(1 + h), "r"(64) : "memory");

    // ---- P (fp16) -> SW128 ----
#pragma unroll
    for (int mt = 0; mt < 2; mt++) {
        const int r0 = half * 32 + mt * 16 + g;
#pragma unroll
        for (int nt = 0; nt < 8; nt++) {
            const int c = nt * 8 + 2 * t;
            *(unsigned*)(P + swz128(r0 * 128 + c * 2)) =
                h2pack(s_[mt][nt][0], s_[mt][nt][1]);
            *(unsigned*)(P + swz128((r0 + 8) * 128 + c * 2)) =
                h2pack(s_[mt][nt][2], s_[mt][nt][3]);
        }
    }
    asm volatile("bar.sync %0, %1;" :: "r"(1 + h), "r"(64) : "memory");

    // ---- O = P @ V (fp16 mma; V via ldsm.trans) ----
    float o[2][4][4];
#pragma unroll
    for (int mt = 0; mt < 2; mt++)
#pragma unroll
        for (int nt = 0; nt < 4; nt++)
#pragma unroll
            for (int r = 0; r < 4; r++) o[mt][nt][r] = 0.0f;

#pragma unroll
    for (int kt = 0; kt < 4; ++kt) {
        unsigned bf[4][2];
#pragma unroll
        for (int nt = 0; nt < 4; nt++)
            ldsm_x2_trans(bf[nt], V + swz64((kt * 16 + (lane & 15)) * 64 + nt * 16));
#pragma unroll
        for (int mt = 0; mt < 2; mt++) {
            unsigned af[4];
            ldsm_x4(af, P + swz128((half * 32 + mt * 16 + la_row) * 128 + kt * 32 + la_col * 2));
#pragma unroll
            for (int nt = 0; nt < 4; nt++)
                mma_f16(o[mt][nt], af, bf[nt]);
        }
    }

    // ============ phase 2: fused out-proj ============
    __syncthreads();

    unsigned short* AO    = smu;
    unsigned short* WPbuf = smu + AO_PLANE;

#pragma unroll
    for (int mt = 0; mt < 2; mt++) {
        const int r0 = half * 32 + mt * 16 + g;
#pragma unroll
        for (int nt = 0; nt < 4; nt++) {
            const int col = h * HDIM + nt * 8 + 2 * t;
            *(unsigned*)&AO[r0 * AO_STRIDE + col]       = h2pack(o[mt][nt][0], o[mt][nt][1]);
            *(unsigned*)&AO[(r0 + 8) * AO_STRIDE + col] = h2pack(o[mt][nt][2], o[mt][nt][3]);
        }
    }

    auto issue_wp = [&](int kt, int buf) {
        unsigned short* bh = WPbuf + buf * WP_PLANE;
        const int ko = kt * 32;
#pragma unroll
        for (int i = 0; i < 2; i++) {
            int j = tid + 512 * i;                 // 0..1023
            const int row = j >> 2, ch = (j & 3) * 8;
            cp_async16(&bh[row * TPAD + ch], WPh + row * 256 + ko + ch);
        }
        asm volatile("cp.async.commit_group;\n");
    };

    issue_wp(0, 0);
    __syncthreads();

    const int wm2 = warp >> 3;
    const int wn2 = warp & 7;

    float oc[2][4][4];
#pragma unroll
    for (int mt = 0; mt < 2; mt++)
#pragma unroll
        for (int nt = 0; nt < 4; nt++)
#pragma unroll
            for (int r = 0; r < 4; r++) oc[mt][nt][r] = 0.0f;

    for (int kt = 0; kt < 8; ++kt) {
        asm volatile("cp.async.wait_group 0;\n" ::: "memory");
        __syncthreads();
        if (kt + 1 < 8) issue_wp(kt + 1, (kt + 1) & 1);

        const unsigned short* Bs = WPbuf + (kt & 1) * WP_PLANE;

#pragma unroll
        for (int ks = 0; ks < 2; ++ks) {
            const int ck = kt * 32 + ks * 16;      // A col
            const int bk = ks * 16;                // B col
            unsigned bf[4][2];
#pragma unroll
            for (int nt = 0; nt < 4; nt++)
                ldsm_x2(bf[nt], Bs + (wn2 * 32 + nt * 8 + lb_row) * TPAD + bk + lb_col);
#pragma unroll
            for (int mt = 0; mt < 2; mt++) {
                unsigned af[4];
                ldsm_x4(af, AO + (wm2 * 32 + mt * 16 + la_row) * AO_STRIDE + ck + la_col);
#pragma unroll
                for (int nt = 0; nt < 4; nt++)
                    mma_f16(oc[mt][nt], af, bf[nt]);
            }
        }
        __syncthreads();
    }

#pragma unroll
    for (int mt = 0; mt < 2; mt++) {
        const int r0 = wm2 * 32 + mt * 16 + g;
#pragma unroll
        for (int nt = 0; nt < 4; nt++) {
            const int col = wn2 * 32 + nt * 8 + 2 * t;
            const float b0 = bp[col], b1 = bp[col + 1];
            float* op0 = out + ((size_t)b * N_TOK + r0)     * DIM_C + col;
            float* op1 = out + ((size_t)b * N_TOK + r0 + 8) * DIM_C + col;
            *(float2*)op0 = make_float2(oc[mt][nt][0] + b0, oc[mt][nt][1] + b1);
            *(float2*)op1 = make_float2(oc[mt][nt][2] + b0, oc[mt][nt][3] + b1);
        }
    }
}

// ---------------------------------------------------------------------------
extern "C" void kernel_launch(void* const* d_in, const int* in_sizes, int n_in,
                              void* d_out, int out_size)
{
    const float* x      = (const float*)d_in[0];
    const float* wq     = (const float*)d_in[1];
    const float* bq     = (const float*)d_in[2];
    const float* wkv    = (const float*)d_in[3];
    const float* bkv    = (const float*)d_in[4];
    const float* wp     = (const float*)d_in[5];
    const float* bp     = (const float*)d_in[6];
    const float* rpb    = (const float*)d_in[7];
    const int*   relidx = (const int*)  d_in[8];
    float* out = (float*)d_out;

    float *bqkv = nullptr, *bias = nullptr;
    unsigned short *qkvh, *wth, *wph;
    cudaGetSymbolAddress((void**)&bqkv, g_bqkv);
    cudaGetSymbolAddress((void**)&bias, g_bias);
    cudaGetSymbolAddress((void**)&qkvh, g_qkvh);
    cudaGetSymbolAddress((void**)&wth,  g_wth);
    cudaGetSymbolAddress((void**)&wph,  g_wph);

    cudaFuncSetAttribute(gemm_qkv,   cudaFuncAttributeMaxDynamicSharedMemorySize, GEMM_SMEM);
    cudaFuncSetAttribute(attn_fused, cudaFuncAttributeMaxDynamicSharedMemorySize, ATTN_SMEM);

    pack_w<<<(QKV_LD * DIM_C + 255) / 256, 256>>>(wq, bq, wkv, bkv, wp, rpb, relidx);

    {
        dim3 grid(QKV_LD / 128, M_ROWS / 128);   // (6, 2048)
        gemm_qkv<<<grid, 256, GEMM_SMEM>>>(x, wth, bqkv, qkvh);
    }
    attn_fused<<<B_WIN, 512, ATTN_SMEM>>>(qkvh, bias, wph, bp, out);
}

// round 15
// speedup vs baseline: 2.4636x; 1.0362x over previous
#include <cuda_runtime.h>
#include <cuda_fp16.h>
#include <cuda_bf16.h>
#include <cstdint>

// ---------------------------------------------------------------------------
// TotalAttention — FP16 tensor pipeline (r13) + prefetched out-proj weights.
// r15 = r14 with the smem overlap fixed: AO / WP1 / WP0 fully disjoint.
//   0) pack_w: wq(*scale)|wkv -> fp16 wqkv^T [768][256]; wp^T fp16; biases;
//      bias table g_bias[h][n][m]
//   1) gemm_qkv: qkv = x @ wqkv + bqkv -> qkv fp16 [M][768]
//   2) attn_fused per window (512 thr):
//      - issue Q/K/V cp.async AND wp slice0 prefetch (2 commit groups)
//      - QK^T (f16 mma, ldsm) + bias + softmax(fp32); P -> SW128; PV
//      - out-proj: AO smem + wp slice0 (prefetched) kt0-3 barrier-free;
//        slice1 loaded during kt0-3; kt4-7 -> d_out fp32
// ---------------------------------------------------------------------------

#define B_WIN   4096
#define N_TOK   64
#define DIM_C   256
#define HEADS   8
#define HDIM    32
#define M_ROWS  (B_WIN * N_TOK)
#define QKV_LD  768
#define SCALE_F 0.17677669529663687f

__device__ unsigned short g_qkvh[(size_t)M_ROWS * QKV_LD];   // fp16, 402 MB
__device__ unsigned short g_wth [QKV_LD * DIM_C];            // wqkv^T fp16
__device__ unsigned short g_wph [DIM_C * DIM_C];             // wp^T fp16
__device__ float g_bqkv[QKV_LD];
__device__ float g_bias[HEADS * N_TOK * N_TOK];

// ---------------------------------------------------------------------------
__device__ __forceinline__ void cp_async16(void* smem_dst, const void* gsrc) {
    unsigned saddr = (unsigned)__cvta_generic_to_shared(smem_dst);
    asm volatile("cp.async.cg.shared.global [%0], [%1], 16;\n"
                 :: "r"(saddr), "l"(gsrc));
}

__device__ __forceinline__ void ldsm_x4(unsigned* r, const void* p) {
    unsigned a = (unsigned)__cvta_generic_to_shared(p);
    asm volatile("ldmatrix.sync.aligned.m8n8.x4.shared.b16 {%0,%1,%2,%3}, [%4];"
                 : "=r"(r[0]), "=r"(r[1]), "=r"(r[2]), "=r"(r[3]) : "r"(a));
}

__device__ __forceinline__ void ldsm_x2(unsigned* r, const void* p) {
    unsigned a = (unsigned)__cvta_generic_to_shared(p);
    asm volatile("ldmatrix.sync.aligned.m8n8.x2.shared.b16 {%0,%1}, [%2];"
                 : "=r"(r[0]), "=r"(r[1]) : "r"(a));
}

__device__ __forceinline__ void ldsm_x2_trans(unsigned* r, const void* p) {
    unsigned a = (unsigned)__cvta_generic_to_shared(p);
    asm volatile("ldmatrix.sync.aligned.m8n8.x2.trans.shared.b16 {%0,%1}, [%2];"
                 : "=r"(r[0]), "=r"(r[1]) : "r"(a));
}

__device__ __forceinline__ void mma_f16(float* c, const unsigned* a, const unsigned* b) {
    asm volatile(
        "mma.sync.aligned.m16n8k16.row.col.f32.f16.f16.f32 "
        "{%0,%1,%2,%3}, {%4,%5,%6,%7}, {%8,%9}, {%0,%1,%2,%3};\n"
        : "+f"(c[0]), "+f"(c[1]), "+f"(c[2]), "+f"(c[3])
        : "r"(a[0]), "r"(a[1]), "r"(a[2]), "r"(a[3]),
          "r"(b[0]), "r"(b[1]));
}

__device__ __forceinline__ unsigned h2pack(float a, float b) {
    __half2 h = __float22half2_rn(make_float2(a, b));
    return *(unsigned*)&h;
}

__device__ __forceinline__ uint32_t swz64(uint32_t off)  { return off ^ ((off >> 3) & 0x30); }
__device__ __forceinline__ uint32_t swz128(uint32_t off) { return off ^ ((off >> 3) & 0x70); }

// ---------------------------------------------------------------------------
__global__ void pack_w(const float* __restrict__ wq, const float* __restrict__ bq,
                       const float* __restrict__ wkv, const float* __restrict__ bkv,
                       const float* __restrict__ wp,
                       const float* __restrict__ rpb, const int* __restrict__ relidx)
{
    int i = blockIdx.x * blockDim.x + threadIdx.x;
    if (i < QKV_LD * DIM_C) {
        int n = i / DIM_C, k = i % DIM_C;
        float v = (n < DIM_C) ? wq[k * DIM_C + n] * SCALE_F
                              : wkv[k * 512 + (n - DIM_C)];
        __half h = __float2half_rn(v);
        g_wth[i] = *(unsigned short*)&h;
    }
    if (i < DIM_C * DIM_C) {
        int n = i / DIM_C, k = i % DIM_C;
        __half h = __float2half_rn(wp[k * DIM_C + n]);
        g_wph[i] = *(unsigned short*)&h;
    }
    if (i < QKV_LD) g_bqkv[i] = (i < DIM_C) ? bq[i] * SCALE_F : bkv[i - DIM_C];
    if (i < HEADS * N_TOK * N_TOK) {
        int h = i >> 12, nm = i & 4095;
        g_bias[i] = rpb[relidx[nm] * HEADS + h];
    }
}

// ---------------------------------------------------------------------------
// qkv GEMM (unchanged from r13)
// ---------------------------------------------------------------------------
#define TPAD 40
#define APLANE (128 * TPAD)
#define BBASE  (2 * APLANE)
#define GEMM_SMEM (4 * APLANE * 2)     // 40960 bytes

__global__ __launch_bounds__(256, 2)
void gemm_qkv(const float* __restrict__ X,
              const unsigned short* __restrict__ Bh_g,
              const float* __restrict__ bias,
              unsigned short* __restrict__ C)
{
    extern __shared__ __align__(16) unsigned short smu[];

    const int tid  = threadIdx.x;
    const int warp = tid >> 5, lane = tid & 31;
    const int wm = warp >> 2, wn = warp & 3;
    const int g  = lane >> 2, t  = lane & 3;
    const size_t n0 = (size_t)blockIdx.x * 128;
    const size_t m0 = (size_t)blockIdx.y * 128;

    const int j0 = tid * 2;
    const int brow0 = j0 >> 2, bcc0 = (j0 & 3) * 8;
    const int brow1 = (j0 + 1) >> 2, bcc1 = ((j0 + 1) & 3) * 8;

    int arow[4], acol[4];
#pragma unroll
    for (int j = 0; j < 4; j++) {
        const int c = tid + 256 * j;
        arow[j] = c >> 3;
        acol[j] = (c & 7) * 4;
    }

    const int la_row = lane & 15, la_col = (lane >> 4) * 8;
    const int lb_row = lane & 7,  lb_col = ((lane >> 3) & 1) * 8;

    float acc[4][4][4];
#pragma unroll
    for (int mt = 0; mt < 4; mt++)
#pragma unroll
        for (int nt = 0; nt < 4; nt++)
#pragma unroll
            for (int r = 0; r < 4; r++) acc[mt][nt][r] = 0.0f;

    auto issue_B = [&](int kt, int buf) {
        unsigned short* bh = smu + BBASE + buf * APLANE;
        const int ko = kt * 32;
        cp_async16(&bh[brow0 * TPAD + bcc0], Bh_g + (n0 + brow0) * 256 + ko + bcc0);
        cp_async16(&bh[brow1 * TPAD + bcc1], Bh_g + (n0 + brow1) * 256 + ko + bcc1);
        asm volatile("cp.async.commit_group;\n");
    };

    auto load_A = [&](int kt, float4* regs) {
        const int ko = kt * 32;
#pragma unroll
        for (int j = 0; j < 4; j++)
            regs[j] = *(const float4*)(X + (m0 + arow[j]) * 256 + ko + acol[j]);
    };

    float4 aReg[4];
    load_A(0, aReg);
    issue_B(0, 0);

    for (int kt = 0; kt < 8; ++kt) {
        asm volatile("cp.async.wait_group 0;\n" ::: "memory");

        {
            unsigned short* ah = smu + (kt & 1) * APLANE;
#pragma unroll
            for (int j = 0; j < 4; j++) {
                const unsigned p0 = h2pack(aReg[j].x, aReg[j].y);
                const unsigned p1 = h2pack(aReg[j].z, aReg[j].w);
                *(unsigned long long*)&ah[arow[j] * TPAD + acol[j]] =
                    (unsigned long long)p0 | ((unsigned long long)p1 << 32);
            }
        }
        __syncthreads();

        if (kt + 1 < 8) {
            load_A(kt + 1, aReg);
            issue_B(kt + 1, (kt + 1) & 1);
        }

        const unsigned short* As = smu + (kt & 1) * APLANE;
        const unsigned short* Bs = smu + BBASE + (kt & 1) * APLANE;

#pragma unroll
        for (int ks = 0; ks < 2; ++ks) {
            const int ck = ks * 16;
            unsigned bf[4][2];
#pragma unroll
            for (int nt = 0; nt < 4; nt++)
                ldsm_x2(bf[nt], Bs + (wn * 32 + nt * 8 + lb_row) * TPAD + ck + lb_col);
#pragma unroll
            for (int mt = 0; mt < 4; mt++) {
                unsigned af[4];
                ldsm_x4(af, As + (wm * 64 + mt * 16 + la_row) * TPAD + ck + la_col);
#pragma unroll
                for (int nt = 0; nt < 4; nt++)
                    mma_f16(acc[mt][nt], af, bf[nt]);
            }
        }
        __syncthreads();
    }

#pragma unroll
    for (int mt = 0; mt < 4; mt++) {
        const size_t r0 = m0 + wm * 64 + mt * 16 + g;
#pragma unroll
        for (int nt = 0; nt < 4; nt++) {
            const size_t col = n0 + wn * 32 + nt * 8 + 2 * t;
            const float b0 = bias[col], b1 = bias[col + 1];
            *(unsigned*)&C[r0 * QKV_LD + col] =
                h2pack(acc[mt][nt][0] + b0, acc[mt][nt][1] + b1);
            *(unsigned*)&C[(r0 + 8) * QKV_LD + col] =
                h2pack(acc[mt][nt][2] + b0, acc[mt][nt][3] + b1);
        }
    }
}

// ---------------------------------------------------------------------------
// Attention + fused out-proj with prefetched wp.
// Smem halfs (ALL phase-2 regions disjoint):
//   phase 1: heads [0, 49152): per head h (base h*6144)
//     Q [0,2048) | K [2048,4096) | V [4096,6144); rows 64B, SW64.
//     P aliases Q+K (rows 128B, SW128).
//   phase 2: AO [0, 16896) stride 264;
//            WP1 [16896, 51712)  (slice1, loaded during kt0-3)
//            WP0 [51712, 86528)  (slice0, prefetched during phase 1;
//                                 also disjoint from heads [0,49152))
// ---------------------------------------------------------------------------
#define HEAD_H   6144
#define AO_STRIDE 264
#define AO_PLANE (64 * AO_STRIDE)       // 16896 halfs
#define WPS_STRIDE 136                  // halfs per wp-slice row
#define WPS_HALFS (256 * WPS_STRIDE)    // 34816 halfs
#define WP1_BASE 16896                  // halfs  [16896, 51712)
#define WP0_BASE 51712                  // halfs  [51712, 86528)
#define ATTN_SMEM ((WP0_BASE + WPS_HALFS) * 2)   // 173056 bytes

__global__ __launch_bounds__(512, 1)
void attn_fused(const unsigned short* __restrict__ qkvh,
                const float* __restrict__ bias,
                const unsigned short* __restrict__ WPh,
                const float* __restrict__ bp,
                float* __restrict__ out)
{
    extern __shared__ __align__(16) unsigned short smu[];
    const int b    = blockIdx.x;
    const int tid  = threadIdx.x;
    const int warp = tid >> 5, lane = tid & 31;
    const int h    = warp >> 1;
    const int half = warp & 1;
    const int g = lane >> 2, t = lane & 3;

    const int la_row = lane & 15, la_col = (lane >> 4) * 8;
    const int lb_row = lane & 7,  lb_col = ((lane >> 3) & 1) * 8;

    // wp slice fill: 4096 chunks16B
    auto issue_wp = [&](int slice, unsigned short* dst) {
#pragma unroll
        for (int i = 0; i < 8; i++) {
            const int j = tid + 512 * i;
            const int r = j >> 4, c = (j & 15) * 8;
            cp_async16(&dst[r * WPS_STRIDE + c], WPh + r * 256 + slice * 128 + c);
        }
        asm volatile("cp.async.commit_group;\n");
    };

    // ---- group A: q/k/v into SW64 smem (6144 chunks, 12/thread) ----
    const size_t gbase = (size_t)b * 64 * QKV_LD;
#pragma unroll
    for (int it = 0; it < 12; ++it) {
        const int i   = tid + it * 512;
        const int ch  = i & 3;
        const int row = (i >> 2) & 63;
        const int hr  = i >> 8;            // 0..23
        const int r   = hr % 3;
        const int hh  = hr / 3;
        const unsigned short* gp = qkvh + gbase + row * QKV_LD
                                   + r * 256 + hh * 32 + ch * 8;
        char* sb = (char*)(smu + hh * HEAD_H + r * 2048);
        cp_async16(sb + swz64(row * 64 + ch * 16), gp);
    }
    asm volatile("cp.async.commit_group;\n");

    // ---- group B: wp slice0 prefetch (disjoint region) ----
    issue_wp(0, smu + WP0_BASE);

    // wait for group A only (<=1 outstanding)
    asm volatile("cp.async.wait_group 1;\n" ::: "memory");
    __syncthreads();

    const char* Q = (const char*)(smu + h * HEAD_H);
    const char* K = Q + 4096;
    const char* V = Q + 8192;
    char* P = (char*)(smu + h * HEAD_H);

    // ---- S = Q @ K^T ----
    float s_[2][8][4];
#pragma unroll
    for (int mt = 0; mt < 2; mt++)
#pragma unroll
        for (int nt = 0; nt < 8; nt++)
#pragma unroll
            for (int r = 0; r < 4; r++) s_[mt][nt][r] = 0.0f;

#pragma unroll
    for (int kt = 0; kt < 2; ++kt) {
        unsigned bf[8][2];
#pragma unroll
        for (int nt = 0; nt < 8; nt++)
            ldsm_x2(bf[nt], K + swz64((nt * 8 + lb_row) * 64 + kt * 32 + lb_col * 2));
#pragma unroll
        for (int mt = 0; mt < 2; mt++) {
            unsigned af[4];
            ldsm_x4(af, Q + swz64((half * 32 + mt * 16 + la_row) * 64 + kt * 32 + la_col * 2));
#pragma unroll
            for (int nt = 0; nt < 8; nt++)
                mma_f16(s_[mt][nt], af, bf[nt]);
        }
    }

    // ---- bias + softmax ----
    const float* bh_tab = bias + h * (N_TOK * N_TOK);
#pragma unroll
    for (int mt = 0; mt < 2; mt++) {
        const int r0 = half * 32 + mt * 16 + g;
#pragma unroll
        for (int nt = 0; nt < 8; nt++) {
            const int c = nt * 8 + 2 * t;
            float2 b0 = *(const float2*)&bh_tab[r0 * 64 + c];
            float2 b1 = *(const float2*)&bh_tab[(r0 + 8) * 64 + c];
            s_[mt][nt][0] += b0.x;  s_[mt][nt][1] += b0.y;
            s_[mt][nt][2] += b1.x;  s_[mt][nt][3] += b1.y;
        }
    }
#pragma unroll
    for (int mt = 0; mt < 2; mt++) {
        float m0 = -1e30f, m1 = -1e30f;
#pragma unroll
        for (int nt = 0; nt < 8; nt++) {
            m0 = fmaxf(m0, fmaxf(s_[mt][nt][0], s_[mt][nt][1]));
            m1 = fmaxf(m1, fmaxf(s_[mt][nt][2], s_[mt][nt][3]));
        }
        m0 = fmaxf(m0, __shfl_xor_sync(0xffffffffu, m0, 1));
        m0 = fmaxf(m0, __shfl_xor_sync(0xffffffffu, m0, 2));
        m1 = fmaxf(m1, __shfl_xor_sync(0xffffffffu, m1, 1));
        m1 = fmaxf(m1, __shfl_xor_sync(0xffffffffu, m1, 2));
        float s0 = 0.0f, s1 = 0.0f;
#pragma unroll
        for (int nt = 0; nt < 8; nt++) {
            s_[mt][nt][0] = __expf(s_[mt][nt][0] - m0);
            s_[mt][nt][1] = __expf(s_[mt][nt][1] - m0);
            s_[mt][nt][2] = __expf(s_[mt][nt][2] - m1);
            s_[mt][nt][3] = __expf(s_[mt][nt][3] - m1);
            s0 += s_[mt][nt][0] + s_[mt][nt][1];
            s1 += s_[mt][nt][2] + s_[mt][nt][3];
        }
        s0 += __shfl_xor_sync(0xffffffffu, s0, 1);
        s0 += __shfl_xor_sync(0xffffffffu, s0, 2);
        s1 += __shfl_xor_sync(0xffffffffu, s1, 1);
        s1 += __shfl_xor_sync(0xffffffffu, s1, 2);
        const float i0 = __frcp_rn(s0), i1 = __frcp_rn(s1);
#pragma unroll
        for (int nt = 0; nt < 8; nt++) {
            s_[mt][nt][0] *= i0;  s_[mt][nt][1] *= i0;
            s_[mt][nt][2] *= i1;  s_[mt][nt][3] *= i1;
        }
    }

    asm volatile("bar.sync %0, %1;" :: "r"(1 + h), "r"(64) : "memory");

    // ---- P -> SW128 ----
#pragma unroll
    for (int mt = 0; mt < 2; mt++) {
        const int r0 = half * 32 + mt * 16 + g;
#pragma unroll
        for (int nt = 0; nt < 8; nt++) {
            const int c = nt * 8 + 2 * t;
            *(unsigned*)(P + swz128(r0 * 128 + c * 2)) =
                h2pack(s_[mt][nt][0], s_[mt][nt][1]);
            *(unsigned*)(P + swz128((r0 + 8) * 128 + c * 2)) =
                h2pack(s_[mt][nt][2], s_[mt][nt][3]);
        }
    }
    asm volatile("bar.sync %0, %1;" :: "r"(1 + h), "r"(64) : "memory");

    // ---- O = P @ V ----
    float o[2][4][4];
#pragma unroll
    for (int mt = 0; mt < 2; mt++)
#pragma unroll
        for (int nt = 0; nt < 4; nt++)
#pragma unroll
            for (int r = 0; r < 4; r++) o[mt][nt][r] = 0.0f;

#pragma unroll
    for (int kt = 0; kt < 4; ++kt) {
        unsigned bf[4][2];
#pragma unroll
        for (int nt = 0; nt < 4; nt++)
            ldsm_x2_trans(bf[nt], V + swz64((kt * 16 + (lane & 15)) * 64 + nt * 16));
#pragma unroll
        for (int mt = 0; mt < 2; mt++) {
            unsigned af[4];
            ldsm_x4(af, P + swz128((half * 32 + mt * 16 + la_row) * 128 + kt * 32 + la_col * 2));
#pragma unroll
            for (int nt = 0; nt < 4; nt++)
                mma_f16(o[mt][nt], af, bf[nt]);
        }
    }

    // ============ phase 2: out-proj ============
    __syncthreads();   // all heads done with Q/K/V/P smem

    unsigned short* AO  = smu;
    unsigned short* WP0 = smu + WP0_BASE;
    unsigned short* WP1 = smu + WP1_BASE;

    // AO stores
#pragma unroll
    for (int mt = 0; mt < 2; mt++) {
        const int r0 = half * 32 + mt * 16 + g;
#pragma unroll
        for (int nt = 0; nt < 4; nt++) {
            const int col = h * HDIM + nt * 8 + 2 * t;
            *(unsigned*)&AO[r0 * AO_STRIDE + col]       = h2pack(o[mt][nt][0], o[mt][nt][1]);
            *(unsigned*)&AO[(r0 + 8) * AO_STRIDE + col] = h2pack(o[mt][nt][2], o[mt][nt][3]);
        }
    }

    // issue wp slice1 (group C) into its own disjoint region
    issue_wp(1, WP1);

    // slice0 ready (wait all but the newest group), AO visible
    asm volatile("cp.async.wait_group 1;\n" ::: "memory");
    __syncthreads();

    const int wm2 = warp >> 3;
    const int wn2 = warp & 7;

    float oc[2][4][4];
#pragma unroll
    for (int mt = 0; mt < 2; mt++)
#pragma unroll
        for (int nt = 0; nt < 4; nt++)
#pragma unroll
            for (int r = 0; r < 4; r++) oc[mt][nt][r] = 0.0f;

    // kt 0..3 from slice0 — no barriers
#pragma unroll
    for (int kt = 0; kt < 4; ++kt) {
#pragma unroll
        for (int ks = 0; ks < 2; ++ks) {
            const int ck = kt * 32 + ks * 16;      // A col
            const int bk = kt * 32 + ks * 16;      // B col within slice0
            unsigned bf[4][2];
#pragma unroll
            for (int nt = 0; nt < 4; nt++)
                ldsm_x2(bf[nt], WP0 + (wn2 * 32 + nt * 8 + lb_row) * WPS_STRIDE + bk + lb_col);
#pragma unroll
            for (int mt = 0; mt < 2; mt++) {
                unsigned af[4];
                ldsm_x4(af, AO + (wm2 * 32 + mt * 16 + la_row) * AO_STRIDE + ck + la_col);
#pragma unroll
                for (int nt = 0; nt < 4; nt++)
                    mma_f16(oc[mt][nt], af, bf[nt]);
            }
        }
    }

    // slice1 ready
    asm volatile("cp.async.wait_group 0;\n" ::: "memory");
    __syncthreads();

    // kt 4..7 from slice1
#pragma unroll
    for (int kt = 0; kt < 4; ++kt) {
#pragma unroll
        for (int ks = 0; ks < 2; ++ks) {
            const int ck = 128 + kt * 32 + ks * 16;  // A col
            const int bk = kt * 32 + ks * 16;        // B col within slice1
            unsigned bf[4][2];
#pragma unroll
            for (int nt = 0; nt < 4; nt++)
                ldsm_x2(bf[nt], WP1 + (wn2 * 32 + nt * 8 + lb_row) * WPS_STRIDE + bk + lb_col);
#pragma unroll
            for (int mt = 0; mt < 2; mt++) {
                unsigned af[4];
                ldsm_x4(af, AO + (wm2 * 32 + mt * 16 + la_row) * AO_STRIDE + ck + la_col);
#pragma unroll
                for (int nt = 0; nt < 4; nt++)
                    mma_f16(oc[mt][nt], af, bf[nt]);
            }
        }
    }

    // epilogue
#pragma unroll
    for (int mt = 0; mt < 2; mt++) {
        const int r0 = wm2 * 32 + mt * 16 + g;
#pragma unroll
        for (int nt = 0; nt < 4; nt++) {
            const int col = wn2 * 32 + nt * 8 + 2 * t;
            const float b0 = bp[col], b1 = bp[col + 1];
            float* op0 = out + ((size_t)b * N_TOK + r0)     * DIM_C + col;
            float* op1 = out + ((size_t)b * N_TOK + r0 + 8) * DIM_C + col;
            *(float2*)op0 = make_float2(oc[mt][nt][0] + b0, oc[mt][nt][1] + b1);
            *(float2*)op1 = make_float2(oc[mt][nt][2] + b0, oc[mt][nt][3] + b1);
        }
    }
}

// ---------------------------------------------------------------------------
extern "C" void kernel_launch(void* const* d_in, const int* in_sizes, int n_in,
                              void* d_out, int out_size)
{
    const float* x      = (const float*)d_in[0];
    const float* wq     = (const float*)d_in[1];
    const float* bq     = (const float*)d_in[2];
    const float* wkv    = (const float*)d_in[3];
    const float* bkv    = (const float*)d_in[4];
    const float* wp     = (const float*)d_in[5];
    const float* bp     = (const float*)d_in[6];
    const float* rpb    = (const float*)d_in[7];
    const int*   relidx = (const int*)  d_in[8];
    float* out = (float*)d_out;

    float *bqkv = nullptr, *bias = nullptr;
    unsigned short *qkvh, *wth, *wph;
    cudaGetSymbolAddress((void**)&bqkv, g_bqkv);
    cudaGetSymbolAddress((void**)&bias, g_bias);
    cudaGetSymbolAddress((void**)&qkvh, g_qkvh);
    cudaGetSymbolAddress((void**)&wth,  g_wth);
    cudaGetSymbolAddress((void**)&wph,  g_wph);

    cudaFuncSetAttribute(gemm_qkv,   cudaFuncAttributeMaxDynamicSharedMemorySize, GEMM_SMEM);
    cudaFuncSetAttribute(attn_fused, cudaFuncAttributeMaxDynamicSharedMemorySize, ATTN_SMEM);

    pack_w<<<(QKV_LD * DIM_C + 255) / 256, 256>>>(wq, bq, wkv, bkv, wp, rpb, relidx);

    {
        dim3 grid(QKV_LD / 128, M_ROWS / 128);   // (6, 2048)
        gemm_qkv<<<grid, 256, GEMM_SMEM>>>(x, wth, bqkv, qkvh);
    }
    attn_fused<<<B_WIN, 512, ATTN_SMEM>>>(qkvh, bias, wph, bp, out);
}

// round 16
// speedup vs baseline: 2.5416x; 1.0317x over previous
#include <cuda_runtime.h>
#include <cuda_fp16.h>
#include <cuda_bf16.h>
#include <cstdint>

// ---------------------------------------------------------------------------
// TotalAttention — FP16 tensor pipeline.
// r16 = r15 + (a) per-head-pair qkv loading in attn (overlapped prologue),
//             (b) 3-stage B pipeline in gemm_qkv.
//   0) pack_w: wq(*scale)|wkv -> fp16 wqkv^T [768][256]; wp^T fp16; biases;
//      bias table g_bias[h][n][m]
//   1) gemm_qkv: qkv = x @ wqkv + bqkv -> qkv fp16 [M][768]
//   2) attn_fused per window (512 thr):
//      - each head pair loads ITS head slice (own commit group) + wp0 prefetch
//      - QK^T (f16 mma, ldsm) + bias + softmax(fp32); P -> SW128; PV
//      - out-proj: AO smem + wp slice0 (prefetched) kt0-3; slice1 during
//        kt0-3; kt4-7 -> d_out fp32
// ---------------------------------------------------------------------------

#define B_WIN   4096
#define N_TOK   64
#define DIM_C   256
#define HEADS   8
#define HDIM    32
#define M_ROWS  (B_WIN * N_TOK)
#define QKV_LD  768
#define SCALE_F 0.17677669529663687f

__device__ unsigned short g_qkvh[(size_t)M_ROWS * QKV_LD];   // fp16, 402 MB
__device__ unsigned short g_wth [QKV_LD * DIM_C];            // wqkv^T fp16
__device__ unsigned short g_wph [DIM_C * DIM_C];             // wp^T fp16
__device__ float g_bqkv[QKV_LD];
__device__ float g_bias[HEADS * N_TOK * N_TOK];

// ---------------------------------------------------------------------------
__device__ __forceinline__ void cp_async16(void* smem_dst, const void* gsrc) {
    unsigned saddr = (unsigned)__cvta_generic_to_shared(smem_dst);
    asm volatile("cp.async.cg.shared.global [%0], [%1], 16;\n"
                 :: "r"(saddr), "l"(gsrc));
}

__device__ __forceinline__ void ldsm_x4(unsigned* r, const void* p) {
    unsigned a = (unsigned)__cvta_generic_to_shared(p);
    asm volatile("ldmatrix.sync.aligned.m8n8.x4.shared.b16 {%0,%1,%2,%3}, [%4];"
                 : "=r"(r[0]), "=r"(r[1]), "=r"(r[2]), "=r"(r[3]) : "r"(a));
}

__device__ __forceinline__ void ldsm_x2(unsigned* r, const void* p) {
    unsigned a = (unsigned)__cvta_generic_to_shared(p);
    asm volatile("ldmatrix.sync.aligned.m8n8.x2.shared.b16 {%0,%1}, [%2];"
                 : "=r"(r[0]), "=r"(r[1]) : "r"(a));
}

__device__ __forceinline__ void ldsm_x2_trans(unsigned* r, const void* p) {
    unsigned a = (unsigned)__cvta_generic_to_shared(p);
    asm volatile("ldmatrix.sync.aligned.m8n8.x2.trans.shared.b16 {%0,%1}, [%2];"
                 : "=r"(r[0]), "=r"(r[1]) : "r"(a));
}

__device__ __forceinline__ void mma_f16(float* c, const unsigned* a, const unsigned* b) {
    asm volatile(
        "mma.sync.aligned.m16n8k16.row.col.f32.f16.f16.f32 "
        "{%0,%1,%2,%3}, {%4,%5,%6,%7}, {%8,%9}, {%0,%1,%2,%3};\n"
        : "+f"(c[0]), "+f"(c[1]), "+f"(c[2]), "+f"(c[3])
        : "r"(a[0]), "r"(a[1]), "r"(a[2]), "r"(a[3]),
          "r"(b[0]), "r"(b[1]));
}

__device__ __forceinline__ unsigned h2pack(float a, float b) {
    __half2 h = __float22half2_rn(make_float2(a, b));
    return *(unsigned*)&h;
}

__device__ __forceinline__ uint32_t swz64(uint32_t off)  { return off ^ ((off >> 3) & 0x30); }
__device__ __forceinline__ uint32_t swz128(uint32_t off) { return off ^ ((off >> 3) & 0x70); }

// ---------------------------------------------------------------------------
__global__ void pack_w(const float* __restrict__ wq, const float* __restrict__ bq,
                       const float* __restrict__ wkv, const float* __restrict__ bkv,
                       const float* __restrict__ wp,
                       const float* __restrict__ rpb, const int* __restrict__ relidx)
{
    int i = blockIdx.x * blockDim.x + threadIdx.x;
    if (i < QKV_LD * DIM_C) {
        int n = i / DIM_C, k = i % DIM_C;
        float v = (n < DIM_C) ? wq[k * DIM_C + n] * SCALE_F
                              : wkv[k * 512 + (n - DIM_C)];
        __half h = __float2half_rn(v);
        g_wth[i] = *(unsigned short*)&h;
    }
    if (i < DIM_C * DIM_C) {
        int n = i / DIM_C, k = i % DIM_C;
        __half h = __float2half_rn(wp[k * DIM_C + n]);
        g_wph[i] = *(unsigned short*)&h;
    }
    if (i < QKV_LD) g_bqkv[i] = (i < DIM_C) ? bq[i] * SCALE_F : bkv[i - DIM_C];
    if (i < HEADS * N_TOK * N_TOK) {
        int h = i >> 12, nm = i & 4095;
        g_bias[i] = rpb[relidx[nm] * HEADS + h];
    }
}

// ---------------------------------------------------------------------------
// qkv GEMM: C[m0..+128, n0..+128] = x @ W^T + bias -> fp16.
// BK=32, 8 kt. A: fp32 regs -> fp16 smem (2 bufs). B: cp.async 3-stage.
// Smem halfs: A bufs [0, 2*APLANE), B bufs [BBASE, BBASE + 3*APLANE).
// ---------------------------------------------------------------------------
#define TPAD 40
#define APLANE (128 * TPAD)            // 5120 halfs
#define BBASE  (2 * APLANE)
#define GEMM_SMEM ((2 * APLANE + 3 * APLANE) * 2)   // 51200 bytes

__global__ __launch_bounds__(256, 2)
void gemm_qkv(const float* __restrict__ X,
              const unsigned short* __restrict__ Bh_g,
              const float* __restrict__ bias,
              unsigned short* __restrict__ C)
{
    extern __shared__ __align__(16) unsigned short smu[];

    const int tid  = threadIdx.x;
    const int warp = tid >> 5, lane = tid & 31;
    const int wm = warp >> 2, wn = warp & 3;
    const int g  = lane >> 2, t  = lane & 3;
    const size_t n0 = (size_t)blockIdx.x * 128;
    const size_t m0 = (size_t)blockIdx.y * 128;

    const int j0 = tid * 2;
    const int brow0 = j0 >> 2, bcc0 = (j0 & 3) * 8;
    const int brow1 = (j0 + 1) >> 2, bcc1 = ((j0 + 1) & 3) * 8;

    int arow[4], acol[4];
#pragma unroll
    for (int j = 0; j < 4; j++) {
        const int c = tid + 256 * j;
        arow[j] = c >> 3;
        acol[j] = (c & 7) * 4;
    }

    const int la_row = lane & 15, la_col = (lane >> 4) * 8;
    const int lb_row = lane & 7,  lb_col = ((lane >> 3) & 1) * 8;

    float acc[4][4][4];
#pragma unroll
    for (int mt = 0; mt < 4; mt++)
#pragma unroll
        for (int nt = 0; nt < 4; nt++)
#pragma unroll
            for (int r = 0; r < 4; r++) acc[mt][nt][r] = 0.0f;

    auto issue_B = [&](int kt, int buf) {
        unsigned short* bh = smu + BBASE + buf * APLANE;
        const int ko = kt * 32;
        cp_async16(&bh[brow0 * TPAD + bcc0], Bh_g + (n0 + brow0) * 256 + ko + bcc0);
        cp_async16(&bh[brow1 * TPAD + bcc1], Bh_g + (n0 + brow1) * 256 + ko + bcc1);
        asm volatile("cp.async.commit_group;\n");
    };

    auto load_A = [&](int kt, float4* regs) {
        const int ko = kt * 32;
#pragma unroll
        for (int j = 0; j < 4; j++)
            regs[j] = *(const float4*)(X + (m0 + arow[j]) * 256 + ko + acol[j]);
    };

    float4 aReg[4];
    load_A(0, aReg);
    issue_B(0, 0);
    issue_B(1, 1);

    for (int kt = 0; kt < 8; ++kt) {
        // B(kt) ready (B(kt+1) may be outstanding); last iter waits all
        if (kt < 7) { asm volatile("cp.async.wait_group 1;\n" ::: "memory"); }
        else        { asm volatile("cp.async.wait_group 0;\n" ::: "memory"); }

        // cvt + STS A slice into buffer kt&1 (last read at compute kt-2)
        {
            unsigned short* ah = smu + (kt & 1) * APLANE;
#pragma unroll
            for (int j = 0; j < 4; j++) {
                const unsigned p0 = h2pack(aReg[j].x, aReg[j].y);
                const unsigned p1 = h2pack(aReg[j].z, aReg[j].w);
                *(unsigned long long*)&ah[arow[j] * TPAD + acol[j]] =
                    (unsigned long long)p0 | ((unsigned long long)p1 << 32);
            }
        }
        __syncthreads();   // publish A(kt) STS + B(kt) arrival

        if (kt + 2 < 8) issue_B(kt + 2, (kt + 2) % 3);
        if (kt + 1 < 8) load_A(kt + 1, aReg);

        const unsigned short* As = smu + (kt & 1) * APLANE;
        const unsigned short* Bs = smu + BBASE + (kt % 3) * APLANE;

#pragma unroll
        for (int ks = 0; ks < 2; ++ks) {
            const int ck = ks * 16;
            unsigned bf[4][2];
#pragma unroll
            for (int nt = 0; nt < 4; nt++)
                ldsm_x2(bf[nt], Bs + (wn * 32 + nt * 8 + lb_row) * TPAD + ck + lb_col);
#pragma unroll
            for (int mt = 0; mt < 4; mt++) {
                unsigned af[4];
                ldsm_x4(af, As + (wm * 64 + mt * 16 + la_row) * TPAD + ck + la_col);
#pragma unroll
                for (int nt = 0; nt < 4; nt++)
                    mma_f16(acc[mt][nt], af, bf[nt]);
            }
        }
        __syncthreads();   // retire buffers before next iter's STS / cp.async
    }

#pragma unroll
    for (int mt = 0; mt < 4; mt++) {
        const size_t r0 = m0 + wm * 64 + mt * 16 + g;
#pragma unroll
        for (int nt = 0; nt < 4; nt++) {
            const size_t col = n0 + wn * 32 + nt * 8 + 2 * t;
            const float b0 = bias[col], b1 = bias[col + 1];
            *(unsigned*)&C[r0 * QKV_LD + col] =
                h2pack(acc[mt][nt][0] + b0, acc[mt][nt][1] + b1);
            *(unsigned*)&C[(r0 + 8) * QKV_LD + col] =
                h2pack(acc[mt][nt][2] + b0, acc[mt][nt][3] + b1);
        }
    }
}

// ---------------------------------------------------------------------------
// Attention + fused out-proj with prefetched wp; per-pair qkv loading.
// Smem halfs (phase-2 regions disjoint):
//   phase 1: heads [0, 49152): per head h (base h*6144)
//     Q [0,2048) | K [2048,4096) | V [4096,6144); rows 64B, SW64.
//     P aliases Q+K (rows 128B, SW128).
//   phase 2: AO [0, 16896) stride 264;
//            WP1 [16896, 51712); WP0 [51712, 86528)
// ---------------------------------------------------------------------------
#define HEAD_H   6144
#define AO_STRIDE 264
#define AO_PLANE (64 * AO_STRIDE)       // 16896 halfs
#define WPS_STRIDE 136
#define WPS_HALFS (256 * WPS_STRIDE)    // 34816 halfs
#define WP1_BASE 16896
#define WP0_BASE 51712
#define ATTN_SMEM ((WP0_BASE + WPS_HALFS) * 2)   // 173056 bytes

__global__ __launch_bounds__(512, 1)
void attn_fused(const unsigned short* __restrict__ qkvh,
                const float* __restrict__ bias,
                const unsigned short* __restrict__ WPh,
                const float* __restrict__ bp,
                float* __restrict__ out)
{
    extern __shared__ __align__(16) unsigned short smu[];
    const int b    = blockIdx.x;
    const int tid  = threadIdx.x;
    const int warp = tid >> 5, lane = tid & 31;
    const int h    = warp >> 1;
    const int half = warp & 1;
    const int g = lane >> 2, t = lane & 3;
    const int wg = tid & 63;             // index within head pair

    const int la_row = lane & 15, la_col = (lane >> 4) * 8;
    const int lb_row = lane & 7,  lb_col = ((lane >> 3) & 1) * 8;

    auto issue_wp = [&](int slice, unsigned short* dst) {
#pragma unroll
        for (int i = 0; i < 8; i++) {
            const int j = tid + 512 * i;
            const int r = j >> 4, c = (j & 15) * 8;
            cp_async16(&dst[r * WPS_STRIDE + c], WPh + r * 256 + slice * 128 + c);
        }
        asm volatile("cp.async.commit_group;\n");
    };

    // ---- group 0 (per thread): OWN head's Q/K/V (768 chunks / pair) ----
    const size_t gbase = (size_t)b * 64 * QKV_LD;
#pragma unroll
    for (int it = 0; it < 12; ++it) {
        const int j   = wg + it * 64;      // 0..767
        const int ch  = j & 3;
        const int row = (j >> 2) & 63;
        const int r   = j >> 8;            // 0=q 1=k 2=v
        const unsigned short* gp = qkvh + gbase + row * QKV_LD
                                   + r * 256 + h * 32 + ch * 8;
        char* sb = (char*)(smu + h * HEAD_H + r * 2048);
        cp_async16(sb + swz64(row * 64 + ch * 16), gp);
    }
    asm volatile("cp.async.commit_group;\n");

    // ---- group 1: wp slice0 prefetch ----
    issue_wp(0, smu + WP0_BASE);

    // own head's data ready (wp0 outstanding); pair barrier publishes
    asm volatile("cp.async.wait_group 1;\n" ::: "memory");
    asm volatile("bar.sync %0, %1;" :: "r"(1 + h), "r"(64) : "memory");

    const char* Q = (const char*)(smu + h * HEAD_H);
    const char* K = Q + 4096;
    const char* V = Q + 8192;
    char* P = (char*)(smu + h * HEAD_H);

    // ---- S = Q @ K^T ----
    float s_[2][8][4];
#pragma unroll
    for (int mt = 0; mt < 2; mt++)
#pragma unroll
        for (int nt = 0; nt < 8; nt++)
#pragma unroll
            for (int r = 0; r < 4; r++) s_[mt][nt][r] = 0.0f;

#pragma unroll
    for (int kt = 0; kt < 2; ++kt) {
        unsigned bf[8][2];
#pragma unroll
        for (int nt = 0; nt < 8; nt++)
            ldsm_x2(bf[nt], K + swz64((nt * 8 + lb_row) * 64 + kt * 32 + lb_col * 2));
#pragma unroll
        for (int mt = 0; mt < 2; mt++) {
            unsigned af[4];
            ldsm_x4(af, Q + swz64((half * 32 + mt * 16 + la_row) * 64 + kt * 32 + la_col * 2));
#pragma unroll
            for (int nt = 0; nt < 8; nt++)
                mma_f16(s_[mt][nt], af, bf[nt]);
        }
    }

    // ---- bias + softmax ----
    const float* bh_tab = bias + h * (N_TOK * N_TOK);
#pragma unroll
    for (int mt = 0; mt < 2; mt++) {
        const int r0 = half * 32 + mt * 16 + g;
#pragma unroll
        for (int nt = 0; nt < 8; nt++) {
            const int c = nt * 8 + 2 * t;
            float2 b0 = *(const float2*)&bh_tab[r0 * 64 + c];
            float2 b1 = *(const float2*)&bh_tab[(r0 + 8) * 64 + c];
            s_[mt][nt][0] += b0.x;  s_[mt][nt][1] += b0.y;
            s_[mt][nt][2] += b1.x;  s_[mt][nt][3] += b1.y;
        }
    }
#pragma unroll
    for (int mt = 0; mt < 2; mt++) {
        float m0 = -1e30f, m1 = -1e30f;
#pragma unroll
        for (int nt = 0; nt < 8; nt++) {
            m0 = fmaxf(m0, fmaxf(s_[mt][nt][0], s_[mt][nt][1]));
            m1 = fmaxf(m1, fmaxf(s_[mt][nt][2], s_[mt][nt][3]));
        }
        m0 = fmaxf(m0, __shfl_xor_sync(0xffffffffu, m0, 1));
        m0 = fmaxf(m0, __shfl_xor_sync(0xffffffffu, m0, 2));
        m1 = fmaxf(m1, __shfl_xor_sync(0xffffffffu, m1, 1));
        m1 = fmaxf(m1, __shfl_xor_sync(0xffffffffu, m1, 2));
        float s0 = 0.0f, s1 = 0.0f;
#pragma unroll
        for (int nt = 0; nt < 8; nt++) {
            s_[mt][nt][0] = __expf(s_[mt][nt][0] - m0);
            s_[mt][nt][1] = __expf(s_[mt][nt][1] - m0);
            s_[mt][nt][2] = __expf(s_[mt][nt][2] - m1);
            s_[mt][nt][3] = __expf(s_[mt][nt][3] - m1);
            s0 += s_[mt][nt][0] + s_[mt][nt][1];
            s1 += s_[mt][nt][2] + s_[mt][nt][3];
        }
        s0 += __shfl_xor_sync(0xffffffffu, s0, 1);
        s0 += __shfl_xor_sync(0xffffffffu, s0, 2);
        s1 += __shfl_xor_sync(0xffffffffu, s1, 1);
        s1 += __shfl_xor_sync(0xffffffffu, s1, 2);
        const float i0 = __frcp_rn(s0), i1 = __frcp_rn(s1);
#pragma unroll
        for (int nt = 0; nt < 8; nt++) {
            s_[mt][nt][0] *= i0;  s_[mt][nt][1] *= i0;
            s_[mt][nt][2] *= i1;  s_[mt][nt][3] *= i1;
        }
    }

    asm volatile("bar.sync %0, %1;" :: "r"(1 + h), "r"(64) : "memory");

    // ---- P -> SW128 ----
#pragma unroll
    for (int mt = 0; mt < 2; mt++) {
        const int r0 = half * 32 + mt * 16 + g;
#pragma unroll
        for (int nt = 0; nt < 8; nt++) {
            const int c = nt * 8 + 2 * t;
            *(unsigned*)(P + swz128(r0 * 128 + c * 2)) =
                h2pack(s_[mt][nt][0], s_[mt][nt][1]);
            *(unsigned*)(P + swz128((r0 + 8) * 128 + c * 2)) =
                h2pack(s_[mt][nt][2], s_[mt][nt][3]);
        }
    }
    asm volatile("bar.sync %0, %1;" :: "r"(1 + h), "r"(64) : "memory");

    // ---- O = P @ V ----
    float o[2][4][4];
#pragma unroll
    for (int mt = 0; mt < 2; mt++)
#pragma unroll
        for (int nt = 0; nt < 4; nt++)
#pragma unroll
            for (int r = 0; r < 4; r++) o[mt][nt][r] = 0.0f;

#pragma unroll
    for (int kt = 0; kt < 4; ++kt) {
        unsigned bf[4][2];
#pragma unroll
        for (int nt = 0; nt < 4; nt++)
            ldsm_x2_trans(bf[nt], V + swz64((kt * 16 + (lane & 15)) * 64 + nt * 16));
#pragma unroll
        for (int mt = 0; mt < 2; mt++) {
            unsigned af[4];
            ldsm_x4(af, P + swz128((half * 32 + mt * 16 + la_row) * 128 + kt * 32 + la_col * 2));
#pragma unroll
            for (int nt = 0; nt < 4; nt++)
                mma_f16(o[mt][nt], af, bf[nt]);
        }
    }

    // ============ phase 2: out-proj ============
    __syncthreads();   // all pairs done with Q/K/V/P smem

    unsigned short* AO  = smu;
    unsigned short* WP0 = smu + WP0_BASE;
    unsigned short* WP1 = smu + WP1_BASE;

#pragma unroll
    for (int mt = 0; mt < 2; mt++) {
        const int r0 = half * 32 + mt * 16 + g;
#pragma unroll
        for (int nt = 0; nt < 4; nt++) {
            const int col = h * HDIM + nt * 8 + 2 * t;
            *(unsigned*)&AO[r0 * AO_STRIDE + col]       = h2pack(o[mt][nt][0], o[mt][nt][1]);
            *(unsigned*)&AO[(r0 + 8) * AO_STRIDE + col] = h2pack(o[mt][nt][2], o[mt][nt][3]);
        }
    }

    // group 2: wp slice1
    issue_wp(1, WP1);

    // slice0 ready, AO visible
    asm volatile("cp.async.wait_group 1;\n" ::: "memory");
    __syncthreads();

    const int wm2 = warp >> 3;
    const int wn2 = warp & 7;

    float oc[2][4][4];
#pragma unroll
    for (int mt = 0; mt < 2; mt++)
#pragma unroll
        for (int nt = 0; nt < 4; nt++)
#pragma unroll
            for (int r = 0; r < 4; r++) oc[mt][nt][r] = 0.0f;

    // kt 0..3 from slice0
#pragma unroll
    for (int kt = 0; kt < 4; ++kt) {
#pragma unroll
        for (int ks = 0; ks < 2; ++ks) {
            const int ck = kt * 32 + ks * 16;
            const int bk = kt * 32 + ks * 16;
            unsigned bf[4][2];
#pragma unroll
            for (int nt = 0; nt < 4; nt++)
                ldsm_x2(bf[nt], WP0 + (wn2 * 32 + nt * 8 + lb_row) * WPS_STRIDE + bk + lb_col);
#pragma unroll
            for (int mt = 0; mt < 2; mt++) {
                unsigned af[4];
                ldsm_x4(af, AO + (wm2 * 32 + mt * 16 + la_row) * AO_STRIDE + ck + la_col);
#pragma unroll
                for (int nt = 0; nt < 4; nt++)
                    mma_f16(oc[mt][nt], af, bf[nt]);
            }
        }
    }

    // slice1 ready
    asm volatile("cp.async.wait_group 0;\n" ::: "memory");
    __syncthreads();

    // kt 4..7 from slice1
#pragma unroll
    for (int kt = 0; kt < 4; ++kt) {
#pragma unroll
        for (int ks = 0; ks < 2; ++ks) {
            const int ck = 128 + kt * 32 + ks * 16;
            const int bk = kt * 32 + ks * 16;
            unsigned bf[4][2];
#pragma unroll
            for (int nt = 0; nt < 4; nt++)
                ldsm_x2(bf[nt], WP1 + (wn2 * 32 + nt * 8 + lb_row) * WPS_STRIDE + bk + lb_col);
#pragma unroll
            for (int mt = 0; mt < 2; mt++) {
                unsigned af[4];
                ldsm_x4(af, AO + (wm2 * 32 + mt * 16 + la_row) * AO_STRIDE + ck + la_col);
#pragma unroll
                for (int nt = 0; nt < 4; nt++)
                    mma_f16(oc[mt][nt], af, bf[nt]);
            }
        }
    }

    // epilogue
#pragma unroll
    for (int mt = 0; mt < 2; mt++) {
        const int r0 = wm2 * 32 + mt * 16 + g;
#pragma unroll
        for (int nt = 0; nt < 4; nt++) {
            const int col = wn2 * 32 + nt * 8 + 2 * t;
            const float b0 = bp[col], b1 = bp[col + 1];
            float* op0 = out + ((size_t)b * N_TOK + r0)     * DIM_C + col;
            float* op1 = out + ((size_t)b * N_TOK + r0 + 8) * DIM_C + col;
            *(float2*)op0 = make_float2(oc[mt][nt][0] + b0, oc[mt][nt][1] + b1);
            *(float2*)op1 = make_float2(oc[mt][nt][2] + b0, oc[mt][nt][3] + b1);
        }
    }
}

// ---------------------------------------------------------------------------
extern "C" void kernel_launch(void* const* d_in, const int* in_sizes, int n_in,
                              void* d_out, int out_size)
{
    const float* x      = (const float*)d_in[0];
    const float* wq     = (const float*)d_in[1];
    const float* bq     = (const float*)d_in[2];
    const float* wkv    = (const float*)d_in[3];
    const float* bkv    = (const float*)d_in[4];
    const float* wp     = (const float*)d_in[5];
    const float* bp     = (const float*)d_in[6];
    const float* rpb    = (const float*)d_in[7];
    const int*   relidx = (const int*)  d_in[8];
    float* out = (float*)d_out;

    float *bqkv = nullptr, *bias = nullptr;
    unsigned short *qkvh, *wth, *wph;
    cudaGetSymbolAddress((void**)&bqkv, g_bqkv);
    cudaGetSymbolAddress((void**)&bias, g_bias);
    cudaGetSymbolAddress((void**)&qkvh, g_qkvh);
    cudaGetSymbolAddress((void**)&wth,  g_wth);
    cudaGetSymbolAddress((void**)&wph,  g_wph);

    cudaFuncSetAttribute(gemm_qkv,   cudaFuncAttributeMaxDynamicSharedMemorySize, GEMM_SMEM);
    cudaFuncSetAttribute(attn_fused, cudaFuncAttributeMaxDynamicSharedMemorySize, ATTN_SMEM);

    pack_w<<<(QKV_LD * DIM_C + 255) / 256, 256>>>(wq, bq, wkv, bkv, wp, rpb, relidx);

    {
        dim3 grid(QKV_LD / 128, M_ROWS / 128);   // (6, 2048)
        gemm_qkv<<<grid, 256, GEMM_SMEM>>>(x, wth, bqkv, qkvh);
    }
    attn_fused<<<B_WIN, 512, ATTN_SMEM>>>(qkvh, bias, wph, bp, out);
}

// round 17
// speedup vs baseline: 2.7091x; 1.0659x over previous
#include <cuda_runtime.h>
#include <cuda_fp16.h>
#include <cuda_bf16.h>
#include <cstdint>

// ---------------------------------------------------------------------------
// TotalAttention — FP16 tensor pipeline.
// r17 = r16 + persistent attention blocks with wp FULLY smem-resident
// (unpadded, custom XOR swizzle) + cross-window qkv prefetch.
//   0) pack_w: wq(*scale)|wkv -> fp16 wqkv^T [768][256]; wp^T fp16; biases;
//      bias table g_bias[h][n][m]
//   1) gemm_qkv: qkv = x @ wqkv + bqkv -> qkv fp16 [M][768]   (r16 3-stage)
//   2) attn_fused: grid = #SMs persistent blocks; per block: load wp once;
//      loop windows: phase1 attention (per-pair prefetched qkv), phase2
//      out-proj vs resident wp (zero waits), prefetch next window's qkv.
// ---------------------------------------------------------------------------

#define B_WIN   4096
#define N_TOK   64
#define DIM_C   256
#define HEADS   8
#define HDIM    32
#define M_ROWS  (B_WIN * N_TOK)
#define QKV_LD  768
#define SCALE_F 0.17677669529663687f

__device__ unsigned short g_qkvh[(size_t)M_ROWS * QKV_LD];   // fp16, 402 MB
__device__ unsigned short g_wth [QKV_LD * DIM_C];            // wqkv^T fp16
__device__ unsigned short g_wph [DIM_C * DIM_C];             // wp^T fp16
__device__ float g_bqkv[QKV_LD];
__device__ float g_bias[HEADS * N_TOK * N_TOK];

// ---------------------------------------------------------------------------
__device__ __forceinline__ void cp_async16(void* smem_dst, const void* gsrc) {
    unsigned saddr = (unsigned)__cvta_generic_to_shared(smem_dst);
    asm volatile("cp.async.cg.shared.global [%0], [%1], 16;\n"
                 :: "r"(saddr), "l"(gsrc));
}

__device__ __forceinline__ void ldsm_x4(unsigned* r, const void* p) {
    unsigned a = (unsigned)__cvta_generic_to_shared(p);
    asm volatile("ldmatrix.sync.aligned.m8n8.x4.shared.b16 {%0,%1,%2,%3}, [%4];"
                 : "=r"(r[0]), "=r"(r[1]), "=r"(r[2]), "=r"(r[3]) : "r"(a));
}

__device__ __forceinline__ void ldsm_x2(unsigned* r, const void* p) {
    unsigned a = (unsigned)__cvta_generic_to_shared(p);
    asm volatile("ldmatrix.sync.aligned.m8n8.x2.shared.b16 {%0,%1}, [%2];"
                 : "=r"(r[0]), "=r"(r[1]) : "r"(a));
}

__device__ __forceinline__ void ldsm_x2_trans(unsigned* r, const void* p) {
    unsigned a = (unsigned)__cvta_generic_to_shared(p);
    asm volatile("ldmatrix.sync.aligned.m8n8.x2.trans.shared.b16 {%0,%1}, [%2];"
                 : "=r"(r[0]), "=r"(r[1]) : "r"(a));
}

__device__ __forceinline__ void mma_f16(float* c, const unsigned* a, const unsigned* b) {
    asm volatile(
        "mma.sync.aligned.m16n8k16.row.col.f32.f16.f16.f32 "
        "{%0,%1,%2,%3}, {%4,%5,%6,%7}, {%8,%9}, {%0,%1,%2,%3};\n"
        : "+f"(c[0]), "+f"(c[1]), "+f"(c[2]), "+f"(c[3])
        : "r"(a[0]), "r"(a[1]), "r"(a[2]), "r"(a[3]),
          "r"(b[0]), "r"(b[1]));
}

__device__ __forceinline__ unsigned h2pack(float a, float b) {
    __half2 h = __float22half2_rn(make_float2(a, b));
    return *(unsigned*)&h;
}

__device__ __forceinline__ uint32_t swz64(uint32_t off)  { return off ^ ((off >> 3) & 0x30); }
__device__ __forceinline__ uint32_t swz128(uint32_t off) { return off ^ ((off >> 3) & 0x70); }
// 256B rows: rotate 16B chunk by row&7 (bits [10:8] -> [6:4])
__device__ __forceinline__ uint32_t swz256(uint32_t off) { return off ^ ((off >> 4) & 0x70); }

// ---------------------------------------------------------------------------
__global__ void pack_w(const float* __restrict__ wq, const float* __restrict__ bq,
                       const float* __restrict__ wkv, const float* __restrict__ bkv,
                       const float* __restrict__ wp,
                       const float* __restrict__ rpb, const int* __restrict__ relidx)
{
    int i = blockIdx.x * blockDim.x + threadIdx.x;
    if (i < QKV_LD * DIM_C) {
        int n = i / DIM_C, k = i % DIM_C;
        float v = (n < DIM_C) ? wq[k * DIM_C + n] * SCALE_F
                              : wkv[k * 512 + (n - DIM_C)];
        __half h = __float2half_rn(v);
        g_wth[i] = *(unsigned short*)&h;
    }
    if (i < DIM_C * DIM_C) {
        int n = i / DIM_C, k = i % DIM_C;
        __half h = __float2half_rn(wp[k * DIM_C + n]);
        g_wph[i] = *(unsigned short*)&h;
    }
    if (i < QKV_LD) g_bqkv[i] = (i < DIM_C) ? bq[i] * SCALE_F : bkv[i - DIM_C];
    if (i < HEADS * N_TOK * N_TOK) {
        int h = i >> 12, nm = i & 4095;
        g_bias[i] = rpb[relidx[nm] * HEADS + h];
    }
}

// ---------------------------------------------------------------------------
// qkv GEMM (r16 verbatim: 3-stage B pipeline)
// ---------------------------------------------------------------------------
#define TPAD 40
#define APLANE (128 * TPAD)
#define BBASE  (2 * APLANE)
#define GEMM_SMEM ((2 * APLANE + 3 * APLANE) * 2)   // 51200 bytes

__global__ __launch_bounds__(256, 2)
void gemm_qkv(const float* __restrict__ X,
              const unsigned short* __restrict__ Bh_g,
              const float* __restrict__ bias,
              unsigned short* __restrict__ C)
{
    extern __shared__ __align__(16) unsigned short smu[];

    const int tid  = threadIdx.x;
    const int warp = tid >> 5, lane = tid & 31;
    const int wm = warp >> 2, wn = warp & 3;
    const int g  = lane >> 2, t  = lane & 3;
    const size_t n0 = (size_t)blockIdx.x * 128;
    const size_t m0 = (size_t)blockIdx.y * 128;

    const int j0 = tid * 2;
    const int brow0 = j0 >> 2, bcc0 = (j0 & 3) * 8;
    const int brow1 = (j0 + 1) >> 2, bcc1 = ((j0 + 1) & 3) * 8;

    int arow[4], acol[4];
#pragma unroll
    for (int j = 0; j < 4; j++) {
        const int c = tid + 256 * j;
        arow[j] = c >> 3;
        acol[j] = (c & 7) * 4;
    }

    const int la_row = lane & 15, la_col = (lane >> 4) * 8;
    const int lb_row = lane & 7,  lb_col = ((lane >> 3) & 1) * 8;

    float acc[4][4][4];
#pragma unroll
    for (int mt = 0; mt < 4; mt++)
#pragma unroll
        for (int nt = 0; nt < 4; nt++)
#pragma unroll
            for (int r = 0; r < 4; r++) acc[mt][nt][r] = 0.0f;

    auto issue_B = [&](int kt, int buf) {
        unsigned short* bh = smu + BBASE + buf * APLANE;
        const int ko = kt * 32;
        cp_async16(&bh[brow0 * TPAD + bcc0], Bh_g + (n0 + brow0) * 256 + ko + bcc0);
        cp_async16(&bh[brow1 * TPAD + bcc1], Bh_g + (n0 + brow1) * 256 + ko + bcc1);
        asm volatile("cp.async.commit_group;\n");
    };

    auto load_A = [&](int kt, float4* regs) {
        const int ko = kt * 32;
#pragma unroll
        for (int j = 0; j < 4; j++)
            regs[j] = *(const float4*)(X + (m0 + arow[j]) * 256 + ko + acol[j]);
    };

    float4 aReg[4];
    load_A(0, aReg);
    issue_B(0, 0);
    issue_B(1, 1);

    for (int kt = 0; kt < 8; ++kt) {
        if (kt < 7) { asm volatile("cp.async.wait_group 1;\n" ::: "memory"); }
        else        { asm volatile("cp.async.wait_group 0;\n" ::: "memory"); }

        {
            unsigned short* ah = smu + (kt & 1) * APLANE;
#pragma unroll
            for (int j = 0; j < 4; j++) {
                const unsigned p0 = h2pack(aReg[j].x, aReg[j].y);
                const unsigned p1 = h2pack(aReg[j].z, aReg[j].w);
                *(unsigned long long*)&ah[arow[j] * TPAD + acol[j]] =
                    (unsigned long long)p0 | ((unsigned long long)p1 << 32);
            }
        }
        __syncthreads();

        if (kt + 2 < 8) issue_B(kt + 2, (kt + 2) % 3);
        if (kt + 1 < 8) load_A(kt + 1, aReg);

        const unsigned short* As = smu + (kt & 1) * APLANE;
        const unsigned short* Bs = smu + BBASE + (kt % 3) * APLANE;

#pragma unroll
        for (int ks = 0; ks < 2; ++ks) {
            const int ck = ks * 16;
            unsigned bf[4][2];
#pragma unroll
            for (int nt = 0; nt < 4; nt++)
                ldsm_x2(bf[nt], Bs + (wn * 32 + nt * 8 + lb_row) * TPAD + ck + lb_col);
#pragma unroll
            for (int mt = 0; mt < 4; mt++) {
                unsigned af[4];
                ldsm_x4(af, As + (wm * 64 + mt * 16 + la_row) * TPAD + ck + la_col);
#pragma unroll
                for (int nt = 0; nt < 4; nt++)
                    mma_f16(acc[mt][nt], af, bf[nt]);
            }
        }
        __syncthreads();
    }

#pragma unroll
    for (int mt = 0; mt < 4; mt++) {
        const size_t r0 = m0 + wm * 64 + mt * 16 + g;
#pragma unroll
        for (int nt = 0; nt < 4; nt++) {
            const size_t col = n0 + wn * 32 + nt * 8 + 2 * t;
            const float b0 = bias[col], b1 = bias[col + 1];
            *(unsigned*)&C[r0 * QKV_LD + col] =
                h2pack(acc[mt][nt][0] + b0, acc[mt][nt][1] + b1);
            *(unsigned*)&C[(r0 + 8) * QKV_LD + col] =
                h2pack(acc[mt][nt][2] + b0, acc[mt][nt][3] + b1);
        }
    }
}

// ---------------------------------------------------------------------------
// Persistent attention + fused out-proj; wp smem-resident.
// Smem halfs:
//   heads [0, 49152): per head h (base h*6144):
//     Q [0,2048) | K [2048,4096) | V [4096,6144); rows 64B, SW64.
//     P aliases Q+K (rows 128B, SW128).  AO [0,16896) aliases slots 0-2
//     during phase 2 (stride 264).
//   WPR [49152, 114688): 2 slices x [256 rows][128 halfs], rows 256B,
//     swz256 swizzle (conflict-free, unpadded). slice s at +s*32768.
// ---------------------------------------------------------------------------
#define HEAD_H   6144
#define AO_STRIDE 264
#define WPR_BASE 49152                  // halfs
#define WPR_SLICE 32768                 // halfs per slice
#define ATTN_SMEM ((WPR_BASE + 2 * WPR_SLICE) * 2)   // 229376 bytes

__global__ __launch_bounds__(512, 1)
void attn_fused(const unsigned short* __restrict__ qkvh,
                const float* __restrict__ bias,
                const unsigned short* __restrict__ WPh,
                const float* __restrict__ bp,
                float* __restrict__ out)
{
    extern __shared__ __align__(16) unsigned short smu[];
    const int tid  = threadIdx.x;
    const int warp = tid >> 5, lane = tid & 31;
    const int h    = warp >> 1;
    const int half = warp & 1;
    const int g = lane >> 2, t = lane & 3;
    const int wg = tid & 63;

    const int la_row = lane & 15, la_col = (lane >> 4) * 8;
    const int lb_row = lane & 7,  lb_col = ((lane >> 3) & 1) * 8;

    // per-pair qkv load for window ww (own head slot), one commit group
    auto load_qkv = [&](int ww) {
        const size_t gbase = (size_t)ww * 64 * QKV_LD;
#pragma unroll
        for (int it = 0; it < 12; ++it) {
            const int j   = wg + it * 64;      // 0..767
            const int ch  = j & 3;
            const int row = (j >> 2) & 63;
            const int r   = j >> 8;            // 0=q 1=k 2=v
            const unsigned short* gp = qkvh + gbase + row * QKV_LD
                                       + r * 256 + h * 32 + ch * 8;
            char* sb = (char*)(smu + h * HEAD_H + r * 2048);
            cp_async16(sb + swz64(row * 64 + ch * 16), gp);
        }
        asm volatile("cp.async.commit_group;\n");
    };

    // ---- block init: wp resident fill (8192 chunks16B) + first qkv ----
    {
#pragma unroll
        for (int i = 0; i < 16; ++i) {
            const int j = tid + 512 * i;
            const int slice = j >> 12;
            const int rr = (j >> 4) & 255;
            const int c  = j & 15;
            char* dst = (char*)(smu + WPR_BASE + slice * WPR_SLICE);
            cp_async16(dst + swz256(rr * 256 + c * 16),
                       WPh + rr * 256 + slice * 128 + c * 8);
        }
        asm volatile("cp.async.commit_group;\n");
    }
    load_qkv(blockIdx.x);
    asm volatile("cp.async.wait_group 0;\n" ::: "memory");
    __syncthreads();

    const char* Q = (const char*)(smu + h * HEAD_H);
    const char* K = Q + 4096;
    const char* V = Q + 8192;
    char* P = (char*)(smu + h * HEAD_H);
    unsigned short* AO = smu;
    const char* WPR = (const char*)(smu + WPR_BASE);
    const int wm2 = warp >> 3;
    const int wn2 = warp & 7;

    for (int w = blockIdx.x; w < B_WIN; w += gridDim.x) {
        const bool last = (w + (int)gridDim.x >= B_WIN);

        // ---- S = Q @ K^T ----
        float s_[2][8][4];
#pragma unroll
        for (int mt = 0; mt < 2; mt++)
#pragma unroll
            for (int nt = 0; nt < 8; nt++)
#pragma unroll
                for (int r = 0; r < 4; r++) s_[mt][nt][r] = 0.0f;

#pragma unroll
        for (int kt = 0; kt < 2; ++kt) {
            unsigned bf[8][2];
#pragma unroll
            for (int nt = 0; nt < 8; nt++)
                ldsm_x2(bf[nt], K + swz64((nt * 8 + lb_row) * 64 + kt * 32 + lb_col * 2));
#pragma unroll
            for (int mt = 0; mt < 2; mt++) {
                unsigned af[4];
                ldsm_x4(af, Q + swz64((half * 32 + mt * 16 + la_row) * 64 + kt * 32 + la_col * 2));
#pragma unroll
                for (int nt = 0; nt < 8; nt++)
                    mma_f16(s_[mt][nt], af, bf[nt]);
            }
        }

        // ---- bias + softmax ----
        const float* bh_tab = bias + h * (N_TOK * N_TOK);
#pragma unroll
        for (int mt = 0; mt < 2; mt++) {
            const int r0 = half * 32 + mt * 16 + g;
#pragma unroll
            for (int nt = 0; nt < 8; nt++) {
                const int c = nt * 8 + 2 * t;
                float2 b0 = *(const float2*)&bh_tab[r0 * 64 + c];
                float2 b1 = *(const float2*)&bh_tab[(r0 + 8) * 64 + c];
                s_[mt][nt][0] += b0.x;  s_[mt][nt][1] += b0.y;
                s_[mt][nt][2] += b1.x;  s_[mt][nt][3] += b1.y;
            }
        }
#pragma unroll
        for (int mt = 0; mt < 2; mt++) {
            float m0 = -1e30f, m1 = -1e30f;
#pragma unroll
            for (int nt = 0; nt < 8; nt++) {
                m0 = fmaxf(m0, fmaxf(s_[mt][nt][0], s_[mt][nt][1]));
                m1 = fmaxf(m1, fmaxf(s_[mt][nt][2], s_[mt][nt][3]));
            }
            m0 = fmaxf(m0, __shfl_xor_sync(0xffffffffu, m0, 1));
            m0 = fmaxf(m0, __shfl_xor_sync(0xffffffffu, m0, 2));
            m1 = fmaxf(m1, __shfl_xor_sync(0xffffffffu, m1, 1));
            m1 = fmaxf(m1, __shfl_xor_sync(0xffffffffu, m1, 2));
            float s0 = 0.0f, s1 = 0.0f;
#pragma unroll
            for (int nt = 0; nt < 8; nt++) {
                s_[mt][nt][0] = __expf(s_[mt][nt][0] - m0);
                s_[mt][nt][1] = __expf(s_[mt][nt][1] - m0);
                s_[mt][nt][2] = __expf(s_[mt][nt][2] - m1);
                s_[mt][nt][3] = __expf(s_[mt][nt][3] - m1);
                s0 += s_[mt][nt][0] + s_[mt][nt][1];
                s1 += s_[mt][nt][2] + s_[mt][nt][3];
            }
            s0 += __shfl_xor_sync(0xffffffffu, s0, 1);
            s0 += __shfl_xor_sync(0xffffffffu, s0, 2);
            s1 += __shfl_xor_sync(0xffffffffu, s1, 1);
            s1 += __shfl_xor_sync(0xffffffffu, s1, 2);
            const float i0 = __frcp_rn(s0), i1 = __frcp_rn(s1);
#pragma unroll
            for (int nt = 0; nt < 8; nt++) {
                s_[mt][nt][0] *= i0;  s_[mt][nt][1] *= i0;
                s_[mt][nt][2] *= i1;  s_[mt][nt][3] *= i1;
            }
        }

        asm volatile("bar.sync %0, %1;" :: "r"(1 + h), "r"(64) : "memory");

        // ---- P -> SW128 ----
#pragma unroll
        for (int mt = 0; mt < 2; mt++) {
            const int r0 = half * 32 + mt * 16 + g;
#pragma unroll
            for (int nt = 0; nt < 8; nt++) {
                const int c = nt * 8 + 2 * t;
                *(unsigned*)(P + swz128(r0 * 128 + c * 2)) =
                    h2pack(s_[mt][nt][0], s_[mt][nt][1]);
                *(unsigned*)(P + swz128((r0 + 8) * 128 + c * 2)) =
                    h2pack(s_[mt][nt][2], s_[mt][nt][3]);
            }
        }
        asm volatile("bar.sync %0, %1;" :: "r"(1 + h), "r"(64) : "memory");

        // ---- O = P @ V ----
        float o[2][4][4];
#pragma unroll
        for (int mt = 0; mt < 2; mt++)
#pragma unroll
            for (int nt = 0; nt < 4; nt++)
#pragma unroll
                for (int r = 0; r < 4; r++) o[mt][nt][r] = 0.0f;

#pragma unroll
        for (int kt = 0; kt < 4; ++kt) {
            unsigned bf[4][2];
#pragma unroll
            for (int nt = 0; nt < 4; nt++)
                ldsm_x2_trans(bf[nt], V + swz64((kt * 16 + (lane & 15)) * 64 + nt * 16));
#pragma unroll
            for (int mt = 0; mt < 2; mt++) {
                unsigned af[4];
                ldsm_x4(af, P + swz128((half * 32 + mt * 16 + la_row) * 128 + kt * 32 + la_col * 2));
#pragma unroll
                for (int nt = 0; nt < 4; nt++)
                    mma_f16(o[mt][nt], af, bf[nt]);
            }
        }

        // ============ phase 2: out-proj (wp resident) ============
        __syncthreads();   // all pairs done with Q/K/V/P smem

#pragma unroll
        for (int mt = 0; mt < 2; mt++) {
            const int r0 = half * 32 + mt * 16 + g;
#pragma unroll
            for (int nt = 0; nt < 4; nt++) {
                const int col = h * HDIM + nt * 8 + 2 * t;
                *(unsigned*)&AO[r0 * AO_STRIDE + col]       = h2pack(o[mt][nt][0], o[mt][nt][1]);
                *(unsigned*)&AO[(r0 + 8) * AO_STRIDE + col] = h2pack(o[mt][nt][2], o[mt][nt][3]);
            }
        }

        // pairs 3..7: prefetch next window's qkv (their slots are dead; AO
        // only occupies slots 0-2)
        if (!last && h >= 3) load_qkv(w + gridDim.x);

        __syncthreads();   // AO visible

        float oc[2][4][4];
#pragma unroll
        for (int mt = 0; mt < 2; mt++)
#pragma unroll
            for (int nt = 0; nt < 4; nt++)
#pragma unroll
                for (int r = 0; r < 4; r++) oc[mt][nt][r] = 0.0f;

#pragma unroll
        for (int kt = 0; kt < 8; ++kt) {
            const int slice = kt >> 2;
#pragma unroll
            for (int ks = 0; ks < 2; ++ks) {
                const int ck  = kt * 32 + ks * 16;          // A col (halfs)
                const int bkh = (kt & 3) * 32 + ks * 16;    // B col within slice
                unsigned bf[4][2];
#pragma unroll
                for (int nt = 0; nt < 4; nt++) {
                    const int row = wn2 * 32 + nt * 8 + lb_row;
                    ldsm_x2(bf[nt], WPR + slice * (WPR_SLICE * 2)
                                    + swz256(row * 256 + (bkh + lb_col) * 2));
                }
#pragma unroll
                for (int mt = 0; mt < 2; mt++) {
                    unsigned af[4];
                    ldsm_x4(af, AO + (wm2 * 32 + mt * 16 + la_row) * AO_STRIDE + ck + la_col);
#pragma unroll
                    for (int nt = 0; nt < 4; nt++)
                        mma_f16(oc[mt][nt], af, bf[nt]);
                }
            }
        }

        // epilogue
#pragma unroll
        for (int mt = 0; mt < 2; mt++) {
            const int r0 = wm2 * 32 + mt * 16 + g;
#pragma unroll
            for (int nt = 0; nt < 4; nt++) {
                const int col = wn2 * 32 + nt * 8 + 2 * t;
                const float b0 = bp[col], b1 = bp[col + 1];
                float* op0 = out + ((size_t)w * N_TOK + r0)     * DIM_C + col;
                float* op1 = out + ((size_t)w * N_TOK + r0 + 8) * DIM_C + col;
                *(float2*)op0 = make_float2(oc[mt][nt][0] + b0, oc[mt][nt][1] + b1);
                *(float2*)op1 = make_float2(oc[mt][nt][2] + b0, oc[mt][nt][3] + b1);
            }
        }

        __syncthreads();   // AO reads done -> slots 0-2 free
        if (!last && h < 3) load_qkv(w + gridDim.x);

        if (!last) {
            asm volatile("cp.async.wait_group 0;\n" ::: "memory");
            asm volatile("bar.sync %0, %1;" :: "r"(1 + h), "r"(64) : "memory");
        }
    }
}

// ---------------------------------------------------------------------------
extern "C" void kernel_launch(void* const* d_in, const int* in_sizes, int n_in,
                              void* d_out, int out_size)
{
    const float* x      = (const float*)d_in[0];
    const float* wq     = (const float*)d_in[1];
    const float* bq     = (const float*)d_in[2];
    const float* wkv    = (const float*)d_in[3];
    const float* bkv    = (const float*)d_in[4];
    const float* wp     = (const float*)d_in[5];
    const float* bp     = (const float*)d_in[6];
    const float* rpb    = (const float*)d_in[7];
    const int*   relidx = (const int*)  d_in[8];
    float* out = (float*)d_out;

    float *bqkv = nullptr, *bias = nullptr;
    unsigned short *qkvh, *wth, *wph;
    cudaGetSymbolAddress((void**)&bqkv, g_bqkv);
    cudaGetSymbolAddress((void**)&bias, g_bias);
    cudaGetSymbolAddress((void**)&qkvh, g_qkvh);
    cudaGetSymbolAddress((void**)&wth,  g_wth);
    cudaGetSymbolAddress((void**)&wph,  g_wph);

    int nsm = 148;
    cudaDeviceGetAttribute(&nsm, cudaDevAttrMultiProcessorCount, 0);
    if (nsm < 1 || nsm > 4096) nsm = 148;

    cudaFuncSetAttribute(gemm_qkv,   cudaFuncAttributeMaxDynamicSharedMemorySize, GEMM_SMEM);
    cudaFuncSetAttribute(attn_fused, cudaFuncAttributeMaxDynamicSharedMemorySize, ATTN_SMEM);

    pack_w<<<(QKV_LD * DIM_C + 255) / 256, 256>>>(wq, bq, wkv, bkv, wp, rpb, relidx);

    {
        dim3 grid(QKV_LD / 128, M_ROWS / 128);   // (6, 2048)
        gemm_qkv<<<grid, 256, GEMM_SMEM>>>(x, wth, bqkv, qkvh);
    }
    attn_fused<<<nsm, 512, ATTN_SMEM>>>(qkvh, bias, wph, bp, out);
}